// round 12
// baseline (speedup 1.0000x reference)
#include <cuda_runtime.h>
#include <cuda_bf16.h>
#include <cuda_fp16.h>
#include <stdint.h>
#include <math.h>

// Problem constants
#define Tn    2048
#define EMB   128
#define NH    8
#define Mv    9      // M
#define Pp    36     // P
#define BT    4096   // B*T
#define D1    1024   // NH*EMB
#define D3    3072   // 3*D1
#define SPAD  40     // padded bf16 smem row stride (80B: ldmatrix conflict-free)
#define STG   (128 * SPAD)            // qkv: elems per stage per array
#define DSMEM (8 * STG * 2)           // qkv: bytes
#define ASTG  (64 * SPAD)             // out: A elems per stage per array
#define BSTG  (128 * SPAD)            // out: B elems per stage per array
#define STAGE_B ((2 * ASTG + 2 * BSTG) * 2) // out: bytes per stage (30720)
#define DSMEM2 (3 * STAGE_B)                // out: 3 stages (92160)

// Scratch (static device arrays; no allocation allowed)
__device__ __half g_q[BT * D1];            // Q fp16 (scaled), token-major
__device__ __half g_K[2 * NH * Tn * EMB];  // K fp16 (scaled), [b][h][t][d]
__device__ __half g_V[2 * NH * Tn * EMB];  // V fp16,          [b][h][t][d]
__device__ int   g_idx[BT * Pp];
__device__ float g_w[BT * Pp];
__device__ float g_part[4][BT * 128];      // split-K partials for out gemm
__device__ unsigned int g_cnt[64];         // split-K arrival counters (per bm)

// pre-split bf16 hi/lo operands
__device__ __nv_bfloat16 g_Xh[BT * EMB],  g_Xl[BT * EMB];     // X
__device__ __nv_bfloat16 g_Wth[D3 * EMB], g_Wtl[D3 * EMB];    // [Wq|Wk|Wv]^T [n][k]
__device__ __nv_bfloat16 g_Wuth[EMB * D1], g_Wutl[EMB * D1];  // Wu^T [128][1024]
__device__ __nv_bfloat16 g_aoh[BT * D1], g_aol[BT * D1];      // attn out hi/lo

// ---------------- threefry-2x32 (JAX-compatible, 20 rounds) ----------------
__device__ __forceinline__ void tf2x32(uint32_t k0, uint32_t k1,
                                       uint32_t& x0, uint32_t& x1) {
  uint32_t ks2 = k0 ^ k1 ^ 0x1BD11BDAu;
  x0 += k0; x1 += k1;
#define TFR(r) { x0 += x1; x1 = (x1 << (r)) | (x1 >> (32 - (r))); x1 ^= x0; }
  TFR(13) TFR(15) TFR(26) TFR(6)
  x0 += k1;  x1 += ks2 + 1u;
  TFR(17) TFR(29) TFR(16) TFR(24)
  x0 += ks2; x1 += k0 + 2u;
  TFR(13) TFR(15) TFR(26) TFR(6)
  x0 += k0;  x1 += k1 + 3u;
  TFR(17) TFR(29) TFR(16) TFR(24)
  x0 += k1;  x1 += ks2 + 4u;
  TFR(13) TFR(15) TFR(26) TFR(6)
  x0 += ks2; x1 += k0 + 5u;
#undef TFR
}

// ---------------- MMA / ldmatrix / cp.async helpers -------------------------
__device__ __forceinline__ void mma16816(float* c, const uint32_t* a, const uint32_t* b) {
  asm volatile(
    "mma.sync.aligned.m16n8k16.row.col.f32.bf16.bf16.f32 "
    "{%0,%1,%2,%3}, {%4,%5,%6,%7}, {%8,%9}, {%0,%1,%2,%3};"
    : "+f"(c[0]), "+f"(c[1]), "+f"(c[2]), "+f"(c[3])
    : "r"(a[0]), "r"(a[1]), "r"(a[2]), "r"(a[3]), "r"(b[0]), "r"(b[1]));
}
__device__ __forceinline__ void ldsm4(uint32_t* r, const __nv_bfloat16* p) {
  uint32_t a = (uint32_t)__cvta_generic_to_shared(p);
  asm volatile("ldmatrix.sync.aligned.m8n8.x4.shared.b16 {%0,%1,%2,%3}, [%4];"
               : "=r"(r[0]), "=r"(r[1]), "=r"(r[2]), "=r"(r[3]) : "r"(a));
}
__device__ __forceinline__ void cpa16(__nv_bfloat16* dst, const __nv_bfloat16* src) {
  uint32_t d = (uint32_t)__cvta_generic_to_shared(dst);
  asm volatile("cp.async.ca.shared.global [%0], [%1], 16;" :: "r"(d), "l"(src));
}
#define CP_COMMIT() asm volatile("cp.async.commit_group;")
#define CP_WAIT2()  asm volatile("cp.async.wait_group 2;" ::: "memory")
#define CP_WAIT1()  asm volatile("cp.async.wait_group 1;" ::: "memory")
#define CP_WAIT0()  asm volatile("cp.async.wait_group 0;" ::: "memory")

// mixed-precision fma: f16 inputs, f32 accumulate (PTX ISA 8.6, sm_100+)
__device__ __forceinline__ void fmah(float& acc, unsigned short a, unsigned short b) {
  asm("fma.rn.f32.f16 %0, %1, %2, %0;" : "+f"(acc) : "h"(a), "h"(b));
}
__device__ __forceinline__ void unpack2(unsigned short& h0, unsigned short& h1, uint32_t w) {
  asm("mov.b32 {%0, %1}, %2;" : "=h"(h0), "=h"(h1) : "r"(w));
}
__device__ __forceinline__ float dot8h(uint4 q, uint4 k) {
  unsigned short qa, qb, ka, kb;
  float a0 = 0.f, a1 = 0.f;
  unpack2(qa, qb, q.x); unpack2(ka, kb, k.x);
  fmah(a0, qa, ka); fmah(a1, qb, kb);
  unpack2(qa, qb, q.y); unpack2(ka, kb, k.y);
  fmah(a0, qa, ka); fmah(a1, qb, kb);
  unpack2(qa, qb, q.z); unpack2(ka, kb, k.z);
  fmah(a0, qa, ka); fmah(a1, qb, kb);
  unpack2(qa, qb, q.w); unpack2(ka, kb, k.w);
  fmah(a0, qa, ka); fmah(a1, qb, kb);
  return a0 + a1;
}

// ---------------- Fused prepass: split X, weights, idx+w --------------------
__device__ void twsplit_body(const float* __restrict__ src,
                             __nv_bfloat16* __restrict__ dh,
                             __nv_bfloat16* __restrict__ dl,
                             int N, int Kd, int nofs, int bx, int by,
                             float* tile /*32x33*/) {
  int tx = threadIdx.x & 31, ty = threadIdx.x >> 5;   // 32 x 8
  int n0 = bx * 32, k0 = by * 32;
  for (int i = ty; i < 32; i += 8)
    tile[i * 33 + tx] = src[(size_t)(k0 + i) * N + n0 + tx];
  __syncthreads();
  for (int i = ty; i < 32; i += 8) {
    float v = tile[tx * 33 + i];                 // src[k0+tx][n0+i]
    __nv_bfloat16 h = __float2bfloat16(v);
    __nv_bfloat16 l = __float2bfloat16(v - __bfloat162float(h));
    size_t o = (size_t)(nofs + n0 + i) * Kd + k0 + tx;
    dh[o] = h; dl[o] = l;
  }
}

__device__ void idxw_body(const float* __restrict__ sp,
                          const float* __restrict__ mvals, int blk) {
  int sub = threadIdx.x >> 6;          // 0..3 (4 tokens per 256-thr block)
  int p = threadIdx.x & 63;
  int token = blk * 4 + sub;           // 0..4095
  int b = token >> 11, t = token & 2047;
  __shared__ float s_mean[4][Mv];
  __shared__ float s_sigma_inv;
  __shared__ int   s_idx[4][Pp];
  __shared__ float s_ptsfl[4][Pp];
  __shared__ float s_dens[4][Pp][Mv];
  __shared__ float s_colinv[4][Mv];

  float dil = sp[0];
  if (p < Mv) {
    float off = __fmul_rn((float)(p - 4), dil);
    float mu  = __fadd_rn((float)t, off);
    mu = fminf(fmaxf(mu, 0.0f), (float)(Tn - 1));
    s_mean[sub][p] = mu;
  }
  if (threadIdx.x == 0) {
    float s = sp[1] + 2.0f;                 // SIGMA_BOOST
    float sigma = log1pf(expf(s)) + 1e-7f;  // softplus + EPS
    s_sigma_inv = 1.0f / sigma;
  }
  __syncthreads();

  if (p < Pp) {
    int m = p >> 2, slot = p & 3;
    float fl = floorf(s_mean[sub][m]);
    float val;
    if (slot == 0) val = fl;
    else if (slot == 1) val = fl + 1.0f;
    else {
      // JAX partitionable threefry (verified in R2)
      uint32_t k2a = 0u, k2b = 1u;
      tf2x32(0u, 42u, k2a, k2b);
      uint32_t i = (uint32_t)(b * 36864 + t * 18 + m * 2 + (slot - 2));
      uint32_t x0 = 0u, x1 = i;
      tf2x32(k2a, k2b, x0, x1);
      uint32_t bits = x0 ^ x1;
      val = (float)(bits & 2047u);
    }
    val = fminf(fmaxf(val, 0.0f), (float)(Tn - 1));
    int iv = (int)val;
    s_idx[sub][p] = iv;
    s_ptsfl[sub][p] = (float)iv;
  }
  __syncthreads();

  if (p < Pp) {
    bool dup = false;
    int my = s_idx[sub][p];
    for (int q = 0; q < p; q++) dup |= (s_idx[sub][q] == my);
    float inv_s = s_sigma_inv;
#pragma unroll
    for (int m = 0; m < Mv; m++) {
      float d = (s_ptsfl[sub][p] - s_mean[sub][m]) * inv_s;
      s_dens[sub][p][m] = dup ? 0.0f : expf(-0.5f * d * d);
    }
  }
  __syncthreads();

  if (p < Mv) {
    float sum = 0.0f;
    for (int q = 0; q < Pp; q++) sum += s_dens[sub][q][p];
    s_colinv[sub][p] = 1.0f / sum;
  }
  __syncthreads();

  if (p < Pp) {
    float w = 0.0f;
#pragma unroll
    for (int m = 0; m < Mv; m++) w += s_dens[sub][p][m] * s_colinv[sub][m] * mvals[m];
    g_idx[token * Pp + p] = s_idx[sub][p];
    g_w[token * Pp + p] = w;
  }
}

__global__ __launch_bounds__(256) void prepass(const float* __restrict__ X,
                                               const float* __restrict__ Wq,
                                               const float* __restrict__ Wk,
                                               const float* __restrict__ Wv,
                                               const float* __restrict__ Wu,
                                               const float* __restrict__ sp,
                                               const float* __restrict__ mv) {
  __shared__ float tile[32 * 33];
  int bid = blockIdx.x;
  if (bid < 512) {                      // split X
    if (bid == 0 && threadIdx.x < 64) g_cnt[threadIdx.x] = 0;  // reset split-K counters
    int e4 = bid * 256 + threadIdx.x;
    float4 v = *(const float4*)(X + e4 * 4);
    float f[4] = {v.x, v.y, v.z, v.w};
    __nv_bfloat16 h[4], l[4];
#pragma unroll
    for (int i = 0; i < 4; i++) {
      h[i] = __float2bfloat16(f[i]);
      l[i] = __float2bfloat16(f[i] - __bfloat162float(h[i]));
    }
    *(uint2*)&g_Xh[e4 * 4] = *(uint2*)h;
    *(uint2*)&g_Xl[e4 * 4] = *(uint2*)l;
  } else if (bid < 1024) {
    int r = bid - 512;                  // 0..511
    int which = r >> 7, sub = r & 127;
    if (which < 3) {                    // Wq/Wk/Wv
      const float* src = (which == 0) ? Wq : ((which == 1) ? Wk : Wv);
      twsplit_body(src, g_Wth, g_Wtl, 1024, 128, which * 1024,
                   sub & 31, sub >> 5, tile);
    } else {                            // Wu
      twsplit_body(Wu, g_Wuth, g_Wutl, 128, 1024, 0,
                   sub & 3, sub >> 2, tile);
    }
  } else {                              // idx + weights: 1024 blocks x 4 tokens
    idxw_body(sp, mv, bid - 1024);
  }
}

// ---------------- shared GEMM inner machinery (128-row variant) -------------
__device__ __forceinline__ void gemm_mma_stage(
    __nv_bfloat16* sAh, __nv_bfloat16* sAl,
    __nv_bfloat16* sBh, __nv_bfloat16* sBl,
    int wm, int wn, int lane, float acc[2][8][4]) {
#pragma unroll
  for (int ks = 0; ks < 32; ks += 16) {
    uint32_t Ah[2][4], Al[2][4], Bh[4][4], Bl[4][4];
#pragma unroll
    for (int mt = 0; mt < 2; mt++) {
      int off = (wm * 32 + mt * 16 + (lane & 15)) * SPAD + ks + 8 * (lane >> 4);
      ldsm4(Ah[mt], &sAh[off]);
      ldsm4(Al[mt], &sAl[off]);
    }
#pragma unroll
    for (int nb = 0; nb < 4; nb++) {
      int off = (wn * 64 + nb * 16 + 8 * ((lane >> 4) & 1) + (lane & 7)) * SPAD
                + ks + 8 * ((lane >> 3) & 1);
      ldsm4(Bh[nb], &sBh[off]);
      ldsm4(Bl[nb], &sBl[off]);
    }
#pragma unroll
    for (int mt = 0; mt < 2; mt++)
#pragma unroll
      for (int nb = 0; nb < 4; nb++) {
        mma16816(acc[mt][nb * 2],     Ah[mt], &Bh[nb][0]);
        mma16816(acc[mt][nb * 2],     Ah[mt], &Bl[nb][0]);
        mma16816(acc[mt][nb * 2],     Al[mt], &Bh[nb][0]);
        mma16816(acc[mt][nb * 2 + 1], Ah[mt], &Bh[nb][2]);
        mma16816(acc[mt][nb * 2 + 1], Ah[mt], &Bl[nb][2]);
        mma16816(acc[mt][nb * 2 + 1], Al[mt], &Bh[nb][2]);
      }
  }
}

// ---------------- Kernel 1: fused QKV projection (tensor core, pipelined) --
__global__ __launch_bounds__(256) void qkv_gemm() {
  extern __shared__ __nv_bfloat16 dsm[];
  __nv_bfloat16* sAh = dsm;
  __nv_bfloat16* sAl = dsm + 2 * STG;
  __nv_bfloat16* sBh = dsm + 4 * STG;
  __nv_bfloat16* sBl = dsm + 6 * STG;
  int bn = blockIdx.x, bm = blockIdx.y;
  int n_glob0 = bn * 128;
  int tid = threadIdx.x, wid = tid >> 5, lane = tid & 31;
  int wm = wid >> 1, wn = wid & 1;
  float acc[2][8][4] = {};

  int r0 = tid >> 2, c0 = tid & 3;
  int r1 = (tid + 256) >> 2, c1 = (tid + 256) & 3;

  auto load_stage = [&](int st, int kc) {
    int so0 = st * STG + r0 * SPAD + c0 * 8;
    int so1 = st * STG + r1 * SPAD + c1 * 8;
    size_t ga0 = (size_t)(bm * 128 + r0) * 128 + kc + c0 * 8;
    size_t ga1 = (size_t)(bm * 128 + r1) * 128 + kc + c1 * 8;
    size_t gb0 = (size_t)(n_glob0 + r0) * 128 + kc + c0 * 8;
    size_t gb1 = (size_t)(n_glob0 + r1) * 128 + kc + c1 * 8;
    cpa16(&sAh[so0], &g_Xh[ga0]);  cpa16(&sAh[so1], &g_Xh[ga1]);
    cpa16(&sAl[so0], &g_Xl[ga0]);  cpa16(&sAl[so1], &g_Xl[ga1]);
    cpa16(&sBh[so0], &g_Wth[gb0]); cpa16(&sBh[so1], &g_Wth[gb1]);
    cpa16(&sBl[so0], &g_Wtl[gb0]); cpa16(&sBl[so1], &g_Wtl[gb1]);
    CP_COMMIT();
  };

  load_stage(0, 0);
#pragma unroll
  for (int kci = 0; kci < 4; kci++) {
    if (kci < 3) load_stage((kci + 1) & 1, (kci + 1) * 32);
    if (kci < 3) { CP_WAIT1(); } else { CP_WAIT0(); }
    __syncthreads();
    int st = (kci & 1) * STG;
    gemm_mma_stage(sAh + st, sAl + st, sBh + st, sBl + st, wm, wn, lane, acc);
    __syncthreads();
  }

  int g = lane >> 2, t = lane & 3;
  int seg = n_glob0 >> 10;                          // 0=Q 1=K 2=V
  float scale = (seg < 2) ? 0.29730177875068026f : 1.0f; // 1/128^0.25
#pragma unroll
  for (int mt = 0; mt < 2; mt++)
#pragma unroll
    for (int nt = 0; nt < 8; nt++) {
      int row = bm * 128 + wm * 32 + mt * 16 + g;
      int col = n_glob0 + wn * 64 + nt * 8 + 2 * t;
      float2 v0 = make_float2(acc[mt][nt][0] * scale, acc[mt][nt][1] * scale);
      float2 v1 = make_float2(acc[mt][nt][2] * scale, acc[mt][nt][3] * scale);
      if (seg == 0) {
        *(__half2*)&g_q[(size_t)row * D1 + col] = __float22half2_rn(v0);
        *(__half2*)&g_q[(size_t)(row + 8) * D1 + col] = __float22half2_rn(v1);
      } else {
        int c = col & 1023, h = c >> 7, d = c & 127;
        int b = row >> 11, tt = row & 2047;
        __half* dst = (seg == 1) ? g_K : g_V;
        size_t base = ((size_t)(b * NH + h) * Tn + tt) * EMB + d;
        *(__half2*)&dst[base] = __float22half2_rn(v0);
        *(__half2*)&dst[base + 8 * EMB] = __float22half2_rn(v1);
      }
    }
}

// ---------------- Kernel 3: gathered attention (fp16 math, f32 accum) ------
__global__ __launch_bounds__(512) void attn_kernel() {
  __shared__ float s_logit[16][Pp];
  __shared__ float s_a[16][Pp];
  int tid = threadIdx.x;
  int wid = tid >> 5, lane = tid & 31;
  int g = lane >> 3, sub = lane & 7;       // QK: 4 groups x 8 lanes
  int half16 = lane >> 4, s16 = lane & 15; // V: 2 halves x 16 lanes
  int token = blockIdx.x * 16 + wid;
  int h = blockIdx.y;
  int b = token >> 11;

  const __half* qp = g_q + (size_t)token * D1 + h * EMB;
  const int*   ip = g_idx + token * Pp;
  const float* wp = g_w + token * Pp;
  const __half* kb = g_K + (size_t)(b * NH + h) * Tn * EMB;
  const __half* vb = g_V + (size_t)(b * NH + h) * Tn * EMB;

  uint4 q0 = *(const uint4*)&qp[sub * 8];        // 8 fp16
  uint4 q1 = *(const uint4*)&qp[64 + sub * 8];   // 8 fp16

#pragma unroll
  for (int it = 0; it < 9; it++) {
    int p = it * 4 + g;
    int j = ip[p];
    const __half* kr = kb + (size_t)j * EMB;
    uint4 k0 = *(const uint4*)&kr[sub * 8];
    uint4 k1 = *(const uint4*)&kr[64 + sub * 8];
    float d = dot8h(q0, k0) + dot8h(q1, k1);
    d += __shfl_xor_sync(0xffffffffu, d, 4);
    d += __shfl_xor_sync(0xffffffffu, d, 2);
    d += __shfl_xor_sync(0xffffffffu, d, 1);
    if (sub == 0) s_logit[wid][p] = wp[p] * d;
  }
  __syncwarp();

  float l0 = s_logit[wid][lane];
  float l1 = (lane < 4) ? s_logit[wid][32 + lane] : -1e30f;
  float mx = fmaxf(l0, l1);
#pragma unroll
  for (int o = 16; o >= 1; o >>= 1)
    mx = fmaxf(mx, __shfl_xor_sync(0xffffffffu, mx, o));
  float a0 = __expf(l0 - mx);
  float a1 = (lane < 4) ? __expf(l1 - mx) : 0.0f;
  float sm = a0 + a1;
#pragma unroll
  for (int o = 16; o >= 1; o >>= 1)
    sm += __shfl_xor_sync(0xffffffffu, sm, o);
  float inv = 1.0f / sm;
  s_a[wid][lane] = a0 * inv;
  if (lane < 4) s_a[wid][32 + lane] = a1 * inv;
  __syncwarp();

  float vacc[8] = {};
#pragma unroll
  for (int it = 0; it < 18; it++) {
    int p = it * 2 + half16;
    int j = ip[p];
    __half ah = __float2half_rn(s_a[wid][p]);
    unsigned short au = __half_as_ushort(ah);
    uint4 v = *(const uint4*)&vb[(size_t)j * EMB + s16 * 8];
    unsigned short v0, v1;
    unpack2(v0, v1, v.x); fmah(vacc[0], v0, au); fmah(vacc[1], v1, au);
    unpack2(v0, v1, v.y); fmah(vacc[2], v0, au); fmah(vacc[3], v1, au);
    unpack2(v0, v1, v.z); fmah(vacc[4], v0, au); fmah(vacc[5], v1, au);
    unpack2(v0, v1, v.w); fmah(vacc[6], v0, au); fmah(vacc[7], v1, au);
  }
#pragma unroll
  for (int d = 0; d < 8; d++)
    vacc[d] += __shfl_xor_sync(0xffffffffu, vacc[d], 16);

  if (half16 == 0) {
    __nv_bfloat16 hh[8], ll[8];
#pragma unroll
    for (int i = 0; i < 8; i++) {
      hh[i] = __float2bfloat16(vacc[i]);
      ll[i] = __float2bfloat16(vacc[i] - __bfloat162float(hh[i]));
    }
    size_t base = (size_t)token * D1 + h * EMB + s16 * 8;
    *(uint4*)&g_aoh[base] = *(uint4*)hh;
    *(uint4*)&g_aol[base] = *(uint4*)ll;
  }
}

// ---------------- Kernel 4: output GEMM (64x128 tile, split-K x4, 3-stage,
//                   fused deterministic reduction via arrival counter) ------
__global__ __launch_bounds__(256) void out_gemm(float* __restrict__ Cout,
                                                const float* __restrict__ bu) {
  extern __shared__ __nv_bfloat16 dsm[];
  __nv_bfloat16* sAh = dsm;                       // 3 * ASTG
  __nv_bfloat16* sAl = dsm + 3 * ASTG;            // 3 * ASTG
  __nv_bfloat16* sBh = dsm + 6 * ASTG;            // 3 * BSTG
  __nv_bfloat16* sBl = dsm + 6 * ASTG + 3 * BSTG; // 3 * BSTG
  __shared__ bool s_last;
  int bm = blockIdx.x, kslice = blockIdx.y;
  int tid = threadIdx.x, wid = tid >> 5, lane = tid & 31;
  int wm = wid >> 2, wn = wid & 3;     // 2 x 4 warps, warp tile 32x32
  float acc[2][4][4] = {};
  int kbase = kslice * 256;

  int rA = tid >> 2, cA = tid & 3;                 // 64 rows x 4 chunks
  int rB0 = tid >> 2, cB0 = tid & 3;               // 128 rows x 4 chunks
  int rB1 = (tid + 256) >> 2, cB1 = (tid + 256) & 3;

  auto load_stage = [&](int st, int kc) {
    int soA = st * ASTG + rA * SPAD + cA * 8;
    int soB0 = st * BSTG + rB0 * SPAD + cB0 * 8;
    int soB1 = st * BSTG + rB1 * SPAD + cB1 * 8;
    size_t ga = (size_t)(bm * 64 + rA) * D1 + kc + cA * 8;
    size_t gb0 = (size_t)rB0 * D1 + kc + cB0 * 8;
    size_t gb1 = (size_t)rB1 * D1 + kc + cB1 * 8;
    cpa16(&sAh[soA], &g_aoh[ga]);
    cpa16(&sAl[soA], &g_aol[ga]);
    cpa16(&sBh[soB0], &g_Wuth[gb0]); cpa16(&sBh[soB1], &g_Wuth[gb1]);
    cpa16(&sBl[soB0], &g_Wutl[gb0]); cpa16(&sBl[soB1], &g_Wutl[gb1]);
    CP_COMMIT();
  };

  load_stage(0, kbase);
  load_stage(1, kbase + 32);
#pragma unroll
  for (int kci = 0; kci < 8; kci++) {
    if (kci + 2 < 8) load_stage((kci + 2) % 3, kbase + (kci + 2) * 32);
    if (kci < 6)      { CP_WAIT2(); }
    else if (kci == 6){ CP_WAIT1(); }
    else              { CP_WAIT0(); }
    __syncthreads();
    int st = kci % 3;
    __nv_bfloat16* pAh = sAh + st * ASTG;
    __nv_bfloat16* pAl = sAl + st * ASTG;
    __nv_bfloat16* pBh = sBh + st * BSTG;
    __nv_bfloat16* pBl = sBl + st * BSTG;
#pragma unroll
    for (int ks = 0; ks < 32; ks += 16) {
      uint32_t Ah[2][4], Al[2][4], Bh[2][4], Bl[2][4];
#pragma unroll
      for (int mt = 0; mt < 2; mt++) {
        int off = (wm * 32 + mt * 16 + (lane & 15)) * SPAD + ks + 8 * (lane >> 4);
        ldsm4(Ah[mt], &pAh[off]);
        ldsm4(Al[mt], &pAl[off]);
      }
#pragma unroll
      for (int nb = 0; nb < 2; nb++) {
        int off = (wn * 32 + nb * 16 + 8 * ((lane >> 4) & 1) + (lane & 7)) * SPAD
                  + ks + 8 * ((lane >> 3) & 1);
        ldsm4(Bh[nb], &pBh[off]);
        ldsm4(Bl[nb], &pBl[off]);
      }
#pragma unroll
      for (int mt = 0; mt < 2; mt++)
#pragma unroll
        for (int nb = 0; nb < 2; nb++) {
          mma16816(acc[mt][nb * 2],     Ah[mt], &Bh[nb][0]);
          mma16816(acc[mt][nb * 2],     Ah[mt], &Bl[nb][0]);
          mma16816(acc[mt][nb * 2],     Al[mt], &Bh[nb][0]);
          mma16816(acc[mt][nb * 2 + 1], Ah[mt], &Bh[nb][2]);
          mma16816(acc[mt][nb * 2 + 1], Ah[mt], &Bl[nb][2]);
          mma16816(acc[mt][nb * 2 + 1], Al[mt], &Bh[nb][2]);
        }
    }
    __syncthreads();
  }

  int g = lane >> 2, t = lane & 3;
  float* dst = g_part[kslice];
#pragma unroll
  for (int mt = 0; mt < 2; mt++)
#pragma unroll
    for (int nt = 0; nt < 4; nt++) {
      int row = bm * 64 + wm * 32 + mt * 16 + g;
      int col = wn * 32 + nt * 8 + 2 * t;
      *(float2*)&dst[(size_t)row * 128 + col] =
          make_float2(acc[mt][nt][0], acc[mt][nt][1]);
      *(float2*)&dst[(size_t)(row + 8) * 128 + col] =
          make_float2(acc[mt][nt][2], acc[mt][nt][3]);
    }

  // ---- split-K fixup: last CTA per bm reduces the 4 partials (deterministic,
  //      fixed read order) and adds bias ----
  __threadfence();
  __syncthreads();
  if (tid == 0) {
    unsigned int old = atomicAdd(&g_cnt[bm], 1u);
    s_last = (old == 3u);
  }
  __syncthreads();
  if (s_last) {
    __threadfence();
    int base4 = bm * 2048;           // float4 index of this bm block (64x128)
#pragma unroll
    for (int it = 0; it < 8; it++) {
      int e4 = base4 + tid + it * 256;
      int col0 = (e4 * 4) & 127;
      float4 s = *(const float4*)(bu + col0);
#pragma unroll
      for (int ks = 0; ks < 4; ks++) {
        float4 p = *(const float4*)(g_part[ks] + e4 * 4);
        s.x += p.x; s.y += p.y; s.z += p.z; s.w += p.w;
      }
      *(float4*)(Cout + e4 * 4) = s;
    }
  }
}

// ---------------- launch ----------------------------------------------------
extern "C" void kernel_launch(void* const* d_in, const int* in_sizes, int n_in,
                              void* d_out, int out_size) {
  const float* x   = (const float*)d_in[0];
  const float* sp  = (const float*)d_in[1];
  const float* mv  = (const float*)d_in[2];
  const float* Wq  = (const float*)d_in[3];
  const float* Wk  = (const float*)d_in[4];
  const float* Wv  = (const float*)d_in[5];
  const float* Wu  = (const float*)d_in[6];
  const float* bu  = (const float*)d_in[7];
  float* out = (float*)d_out;

  static bool attr_done = false;
  if (!attr_done) {
    cudaFuncSetAttribute(qkv_gemm, cudaFuncAttributeMaxDynamicSharedMemorySize, DSMEM);
    cudaFuncSetAttribute(out_gemm, cudaFuncAttributeMaxDynamicSharedMemorySize, DSMEM2);
    attr_done = true;
  }

  prepass<<<2048, 256>>>(x, Wq, Wk, Wv, Wu, sp, mv);
  qkv_gemm<<<dim3(24, 32), 256, DSMEM>>>();
  attn_kernel<<<dim3(256, 8), 512>>>();
  out_gemm<<<dim3(64, 4), 256, DSMEM2>>>(out, bu);
}

// round 13
// speedup vs baseline: 1.0037x; 1.0037x over previous
#include <cuda_runtime.h>
#include <cuda_bf16.h>
#include <cuda_fp16.h>
#include <stdint.h>
#include <math.h>

// Problem constants
#define Tn    2048
#define EMB   128
#define NH    8
#define Mv    9      // M
#define Pp    36     // P
#define BT    4096   // B*T
#define D1    1024   // NH*EMB
#define D3    3072   // 3*D1
#define SPAD  40     // padded bf16 smem row stride (80B: ldmatrix conflict-free)
#define STG   (128 * SPAD)            // qkv: elems per stage per array
#define DSMEM (8 * STG * 2)           // qkv: bytes
#define ASTG  (64 * SPAD)             // out: A elems per stage per array
#define BSTG  (128 * SPAD)            // out: B elems per stage per array
#define DSMEM2 ((4 * ASTG + 4 * BSTG) * 2)  // out: bytes (61440)

// Scratch (static device arrays; no allocation allowed)
__device__ __half g_q[BT * D1];            // Q fp16 (scaled), token-major
__device__ __half g_K[2 * NH * Tn * EMB];  // K fp16 (scaled), [b][h][t][d]
__device__ __half g_V[2 * NH * Tn * EMB];  // V fp16,          [b][h][t][d]
__device__ int   g_idx[BT * Pp];           // element offsets (j*EMB)
__device__ float g_w[BT * Pp];
__device__ float g_part[8][BT * 128];      // split-K partials for out gemm

// pre-split bf16 hi/lo operands
__device__ __nv_bfloat16 g_Xh[BT * EMB],  g_Xl[BT * EMB];     // X
__device__ __nv_bfloat16 g_Wth[D3 * EMB], g_Wtl[D3 * EMB];    // [Wq|Wk|Wv]^T [n][k]
__device__ __nv_bfloat16 g_Wuth[EMB * D1], g_Wutl[EMB * D1];  // Wu^T [128][1024]
__device__ __nv_bfloat16 g_aoh[BT * D1], g_aol[BT * D1];      // attn out hi/lo

// ---------------- threefry-2x32 (JAX-compatible, 20 rounds) ----------------
__device__ __forceinline__ void tf2x32(uint32_t k0, uint32_t k1,
                                       uint32_t& x0, uint32_t& x1) {
  uint32_t ks2 = k0 ^ k1 ^ 0x1BD11BDAu;
  x0 += k0; x1 += k1;
#define TFR(r) { x0 += x1; x1 = (x1 << (r)) | (x1 >> (32 - (r))); x1 ^= x0; }
  TFR(13) TFR(15) TFR(26) TFR(6)
  x0 += k1;  x1 += ks2 + 1u;
  TFR(17) TFR(29) TFR(16) TFR(24)
  x0 += ks2; x1 += k0 + 2u;
  TFR(13) TFR(15) TFR(26) TFR(6)
  x0 += k0;  x1 += k1 + 3u;
  TFR(17) TFR(29) TFR(16) TFR(24)
  x0 += k1;  x1 += ks2 + 4u;
  TFR(13) TFR(15) TFR(26) TFR(6)
  x0 += ks2; x1 += k0 + 5u;
#undef TFR
}

// ---------------- MMA / ldmatrix / cp.async helpers -------------------------
__device__ __forceinline__ void mma16816(float* c, const uint32_t* a, const uint32_t* b) {
  asm volatile(
    "mma.sync.aligned.m16n8k16.row.col.f32.bf16.bf16.f32 "
    "{%0,%1,%2,%3}, {%4,%5,%6,%7}, {%8,%9}, {%0,%1,%2,%3};"
    : "+f"(c[0]), "+f"(c[1]), "+f"(c[2]), "+f"(c[3])
    : "r"(a[0]), "r"(a[1]), "r"(a[2]), "r"(a[3]), "r"(b[0]), "r"(b[1]));
}
__device__ __forceinline__ void ldsm4(uint32_t* r, const __nv_bfloat16* p) {
  uint32_t a = (uint32_t)__cvta_generic_to_shared(p);
  asm volatile("ldmatrix.sync.aligned.m8n8.x4.shared.b16 {%0,%1,%2,%3}, [%4];"
               : "=r"(r[0]), "=r"(r[1]), "=r"(r[2]), "=r"(r[3]) : "r"(a));
}
__device__ __forceinline__ void cpa16(__nv_bfloat16* dst, const __nv_bfloat16* src) {
  uint32_t d = (uint32_t)__cvta_generic_to_shared(dst);
  asm volatile("cp.async.ca.shared.global [%0], [%1], 16;" :: "r"(d), "l"(src));
}
#define CP_COMMIT() asm volatile("cp.async.commit_group;")
#define CP_WAIT1()  asm volatile("cp.async.wait_group 1;" ::: "memory")
#define CP_WAIT0()  asm volatile("cp.async.wait_group 0;" ::: "memory")

// mixed-precision fma: f16 inputs, f32 accumulate (PTX ISA 8.6, sm_100+)
__device__ __forceinline__ void fmah(float& acc, unsigned short a, unsigned short b) {
  asm("fma.rn.f32.f16 %0, %1, %2, %0;" : "+f"(acc) : "h"(a), "h"(b));
}
__device__ __forceinline__ void unpack2(unsigned short& h0, unsigned short& h1, uint32_t w) {
  asm("mov.b32 {%0, %1}, %2;" : "=h"(h0), "=h"(h1) : "r"(w));
}
__device__ __forceinline__ float dot8h(uint4 q, uint4 k) {
  unsigned short qa, qb, ka, kb;
  float a0 = 0.f, a1 = 0.f;
  unpack2(qa, qb, q.x); unpack2(ka, kb, k.x);
  fmah(a0, qa, ka); fmah(a1, qb, kb);
  unpack2(qa, qb, q.y); unpack2(ka, kb, k.y);
  fmah(a0, qa, ka); fmah(a1, qb, kb);
  unpack2(qa, qb, q.z); unpack2(ka, kb, k.z);
  fmah(a0, qa, ka); fmah(a1, qb, kb);
  unpack2(qa, qb, q.w); unpack2(ka, kb, k.w);
  fmah(a0, qa, ka); fmah(a1, qb, kb);
  return a0 + a1;
}

// ---------------- Fused prepass: split X, weights, idx+w --------------------
__device__ void twsplit_body(const float* __restrict__ src,
                             __nv_bfloat16* __restrict__ dh,
                             __nv_bfloat16* __restrict__ dl,
                             int N, int Kd, int nofs, int bx, int by,
                             float* tile /*32x33*/) {
  int tx = threadIdx.x & 31, ty = threadIdx.x >> 5;   // 32 x 8
  int n0 = bx * 32, k0 = by * 32;
  for (int i = ty; i < 32; i += 8)
    tile[i * 33 + tx] = src[(size_t)(k0 + i) * N + n0 + tx];
  __syncthreads();
  for (int i = ty; i < 32; i += 8) {
    float v = tile[tx * 33 + i];                 // src[k0+tx][n0+i]
    __nv_bfloat16 h = __float2bfloat16(v);
    __nv_bfloat16 l = __float2bfloat16(v - __bfloat162float(h));
    size_t o = (size_t)(nofs + n0 + i) * Kd + k0 + tx;
    dh[o] = h; dl[o] = l;
  }
}

__device__ void idxw_body(const float* __restrict__ sp,
                          const float* __restrict__ mvals, int blk) {
  int sub = threadIdx.x >> 6;          // 0..3 (4 tokens per 256-thr block)
  int p = threadIdx.x & 63;
  int token = blk * 4 + sub;           // 0..4095
  int b = token >> 11, t = token & 2047;
  __shared__ float s_mean[4][Mv];
  __shared__ float s_sigma_inv;
  __shared__ int   s_idx[4][Pp];
  __shared__ float s_ptsfl[4][Pp];
  __shared__ float s_dens[4][Pp][Mv];
  __shared__ float s_colinv[4][Mv];

  float dil = sp[0];
  if (p < Mv) {
    float off = __fmul_rn((float)(p - 4), dil);
    float mu  = __fadd_rn((float)t, off);
    mu = fminf(fmaxf(mu, 0.0f), (float)(Tn - 1));
    s_mean[sub][p] = mu;
  }
  if (threadIdx.x == 0) {
    float s = sp[1] + 2.0f;                 // SIGMA_BOOST
    float sigma = log1pf(expf(s)) + 1e-7f;  // softplus + EPS
    s_sigma_inv = 1.0f / sigma;
  }
  __syncthreads();

  if (p < Pp) {
    int m = p >> 2, slot = p & 3;
    float fl = floorf(s_mean[sub][m]);
    float val;
    if (slot == 0) val = fl;
    else if (slot == 1) val = fl + 1.0f;
    else {
      // JAX partitionable threefry (verified in R2)
      uint32_t k2a = 0u, k2b = 1u;
      tf2x32(0u, 42u, k2a, k2b);
      uint32_t i = (uint32_t)(b * 36864 + t * 18 + m * 2 + (slot - 2));
      uint32_t x0 = 0u, x1 = i;
      tf2x32(k2a, k2b, x0, x1);
      uint32_t bits = x0 ^ x1;
      val = (float)(bits & 2047u);
    }
    val = fminf(fmaxf(val, 0.0f), (float)(Tn - 1));
    int iv = (int)val;
    s_idx[sub][p] = iv;
    s_ptsfl[sub][p] = (float)iv;
  }
  __syncthreads();

  if (p < Pp) {
    bool dup = false;
    int my = s_idx[sub][p];
    for (int q = 0; q < p; q++) dup |= (s_idx[sub][q] == my);
    float inv_s = s_sigma_inv;
#pragma unroll
    for (int m = 0; m < Mv; m++) {
      float d = (s_ptsfl[sub][p] - s_mean[sub][m]) * inv_s;
      s_dens[sub][p][m] = dup ? 0.0f : expf(-0.5f * d * d);
    }
  }
  __syncthreads();

  if (p < Mv) {
    float sum = 0.0f;
    for (int q = 0; q < Pp; q++) sum += s_dens[sub][q][p];
    s_colinv[sub][p] = 1.0f / sum;
  }
  __syncthreads();

  if (p < Pp) {
    float w = 0.0f;
#pragma unroll
    for (int m = 0; m < Mv; m++) w += s_dens[sub][p][m] * s_colinv[sub][m] * mvals[m];
    g_idx[token * Pp + p] = s_idx[sub][p] * EMB;   // element offset for attn
    g_w[token * Pp + p] = w;
  }
}

__global__ __launch_bounds__(256) void prepass(const float* __restrict__ X,
                                               const float* __restrict__ Wq,
                                               const float* __restrict__ Wk,
                                               const float* __restrict__ Wv,
                                               const float* __restrict__ Wu,
                                               const float* __restrict__ sp,
                                               const float* __restrict__ mv) {
  __shared__ float tile[32 * 33];
  int bid = blockIdx.x;
  if (bid < 512) {                      // split X
    int e4 = bid * 256 + threadIdx.x;
    float4 v = *(const float4*)(X + e4 * 4);
    float f[4] = {v.x, v.y, v.z, v.w};
    __nv_bfloat16 h[4], l[4];
#pragma unroll
    for (int i = 0; i < 4; i++) {
      h[i] = __float2bfloat16(f[i]);
      l[i] = __float2bfloat16(f[i] - __bfloat162float(h[i]));
    }
    *(uint2*)&g_Xh[e4 * 4] = *(uint2*)h;
    *(uint2*)&g_Xl[e4 * 4] = *(uint2*)l;
  } else if (bid < 1024) {
    int r = bid - 512;                  // 0..511
    int which = r >> 7, sub = r & 127;
    if (which < 3) {                    // Wq/Wk/Wv
      const float* src = (which == 0) ? Wq : ((which == 1) ? Wk : Wv);
      twsplit_body(src, g_Wth, g_Wtl, 1024, 128, which * 1024,
                   sub & 31, sub >> 5, tile);
    } else {                            // Wu
      twsplit_body(Wu, g_Wuth, g_Wutl, 128, 1024, 0,
                   sub & 3, sub >> 2, tile);
    }
  } else {                              // idx + weights: 1024 blocks x 4 tokens
    idxw_body(sp, mv, bid - 1024);
  }
}

// ---------------- shared GEMM inner machinery (128-row variant) -------------
__device__ __forceinline__ void gemm_mma_stage(
    __nv_bfloat16* sAh, __nv_bfloat16* sAl,
    __nv_bfloat16* sBh, __nv_bfloat16* sBl,
    int wm, int wn, int lane, float acc[2][8][4]) {
#pragma unroll
  for (int ks = 0; ks < 32; ks += 16) {
    uint32_t Ah[2][4], Al[2][4], Bh[4][4], Bl[4][4];
#pragma unroll
    for (int mt = 0; mt < 2; mt++) {
      int off = (wm * 32 + mt * 16 + (lane & 15)) * SPAD + ks + 8 * (lane >> 4);
      ldsm4(Ah[mt], &sAh[off]);
      ldsm4(Al[mt], &sAl[off]);
    }
#pragma unroll
    for (int nb = 0; nb < 4; nb++) {
      int off = (wn * 64 + nb * 16 + 8 * ((lane >> 4) & 1) + (lane & 7)) * SPAD
                + ks + 8 * ((lane >> 3) & 1);
      ldsm4(Bh[nb], &sBh[off]);
      ldsm4(Bl[nb], &sBl[off]);
    }
#pragma unroll
    for (int mt = 0; mt < 2; mt++)
#pragma unroll
      for (int nb = 0; nb < 4; nb++) {
        mma16816(acc[mt][nb * 2],     Ah[mt], &Bh[nb][0]);
        mma16816(acc[mt][nb * 2],     Ah[mt], &Bl[nb][0]);
        mma16816(acc[mt][nb * 2],     Al[mt], &Bh[nb][0]);
        mma16816(acc[mt][nb * 2 + 1], Ah[mt], &Bh[nb][2]);
        mma16816(acc[mt][nb * 2 + 1], Ah[mt], &Bl[nb][2]);
        mma16816(acc[mt][nb * 2 + 1], Al[mt], &Bh[nb][2]);
      }
  }
}

// ---------------- Kernel 1: fused QKV projection (tensor core, pipelined) --
__global__ __launch_bounds__(256) void qkv_gemm() {
  extern __shared__ __nv_bfloat16 dsm[];
  __nv_bfloat16* sAh = dsm;
  __nv_bfloat16* sAl = dsm + 2 * STG;
  __nv_bfloat16* sBh = dsm + 4 * STG;
  __nv_bfloat16* sBl = dsm + 6 * STG;
  int bn = blockIdx.x, bm = blockIdx.y;
  int n_glob0 = bn * 128;
  int tid = threadIdx.x, wid = tid >> 5, lane = tid & 31;
  int wm = wid >> 1, wn = wid & 1;
  float acc[2][8][4] = {};

  int r0 = tid >> 2, c0 = tid & 3;
  int r1 = (tid + 256) >> 2, c1 = (tid + 256) & 3;

  auto load_stage = [&](int st, int kc) {
    int so0 = st * STG + r0 * SPAD + c0 * 8;
    int so1 = st * STG + r1 * SPAD + c1 * 8;
    size_t ga0 = (size_t)(bm * 128 + r0) * 128 + kc + c0 * 8;
    size_t ga1 = (size_t)(bm * 128 + r1) * 128 + kc + c1 * 8;
    size_t gb0 = (size_t)(n_glob0 + r0) * 128 + kc + c0 * 8;
    size_t gb1 = (size_t)(n_glob0 + r1) * 128 + kc + c1 * 8;
    cpa16(&sAh[so0], &g_Xh[ga0]);  cpa16(&sAh[so1], &g_Xh[ga1]);
    cpa16(&sAl[so0], &g_Xl[ga0]);  cpa16(&sAl[so1], &g_Xl[ga1]);
    cpa16(&sBh[so0], &g_Wth[gb0]); cpa16(&sBh[so1], &g_Wth[gb1]);
    cpa16(&sBl[so0], &g_Wtl[gb0]); cpa16(&sBl[so1], &g_Wtl[gb1]);
    CP_COMMIT();
  };

  load_stage(0, 0);
#pragma unroll
  for (int kci = 0; kci < 4; kci++) {
    if (kci < 3) load_stage((kci + 1) & 1, (kci + 1) * 32);
    if (kci < 3) { CP_WAIT1(); } else { CP_WAIT0(); }
    __syncthreads();
    int st = (kci & 1) * STG;
    gemm_mma_stage(sAh + st, sAl + st, sBh + st, sBl + st, wm, wn, lane, acc);
    __syncthreads();
  }

  int g = lane >> 2, t = lane & 3;
  int seg = n_glob0 >> 10;                          // 0=Q 1=K 2=V
  float scale = (seg < 2) ? 0.29730177875068026f : 1.0f; // 1/128^0.25
#pragma unroll
  for (int mt = 0; mt < 2; mt++)
#pragma unroll
    for (int nt = 0; nt < 8; nt++) {
      int row = bm * 128 + wm * 32 + mt * 16 + g;
      int col = n_glob0 + wn * 64 + nt * 8 + 2 * t;
      float2 v0 = make_float2(acc[mt][nt][0] * scale, acc[mt][nt][1] * scale);
      float2 v1 = make_float2(acc[mt][nt][2] * scale, acc[mt][nt][3] * scale);
      if (seg == 0) {
        *(__half2*)&g_q[(size_t)row * D1 + col] = __float22half2_rn(v0);
        *(__half2*)&g_q[(size_t)(row + 8) * D1 + col] = __float22half2_rn(v1);
      } else {
        int c = col & 1023, h = c >> 7, d = c & 127;
        int b = row >> 11, tt = row & 2047;
        __half* dst = (seg == 1) ? g_K : g_V;
        size_t base = ((size_t)(b * NH + h) * Tn + tt) * EMB + d;
        *(__half2*)&dst[base] = __float22half2_rn(v0);
        *(__half2*)&dst[base + 8 * EMB] = __float22half2_rn(v1);
      }
    }
}

// ---------------- Kernel 3: gathered attention (fp16 math, f32 accum) ------
__global__ __launch_bounds__(512) void attn_kernel() {
  __shared__ float s_logit[16][Pp];
  __shared__ float s_a[16][Pp];
  int tid = threadIdx.x;
  int wid = tid >> 5, lane = tid & 31;
  int g = lane >> 3, sub = lane & 7;       // QK: 4 groups x 8 lanes
  int half16 = lane >> 4, s16 = lane & 15; // V: 2 halves x 16 lanes
  int token = blockIdx.x * 16 + wid;
  int h = blockIdx.y;
  int b = token >> 11;

  const __half* qp = g_q + (size_t)token * D1 + h * EMB;
  const int*   ip = g_idx + token * Pp;
  const float* wp = g_w + token * Pp;
  const __half* kb = g_K + (size_t)(b * NH + h) * Tn * EMB;
  const __half* vb = g_V + (size_t)(b * NH + h) * Tn * EMB;

  uint4 q0 = *(const uint4*)&qp[sub * 8];        // 8 fp16
  uint4 q1 = *(const uint4*)&qp[64 + sub * 8];   // 8 fp16

#pragma unroll
  for (int it = 0; it < 9; it++) {
    int p = it * 4 + g;
    int j = ip[p];                                // element offset (j*EMB)
    const __half* kr = kb + j;
    uint4 k0 = *(const uint4*)&kr[sub * 8];
    uint4 k1 = *(const uint4*)&kr[64 + sub * 8];
    float d = dot8h(q0, k0) + dot8h(q1, k1);
    d += __shfl_xor_sync(0xffffffffu, d, 4);
    d += __shfl_xor_sync(0xffffffffu, d, 2);
    d += __shfl_xor_sync(0xffffffffu, d, 1);
    if (sub == 0) s_logit[wid][p] = wp[p] * d;
  }
  __syncwarp();

  float l0 = s_logit[wid][lane];
  float l1 = (lane < 4) ? s_logit[wid][32 + lane] : -1e30f;
  float mx = fmaxf(l0, l1);
#pragma unroll
  for (int o = 16; o >= 1; o >>= 1)
    mx = fmaxf(mx, __shfl_xor_sync(0xffffffffu, mx, o));
  float a0 = __expf(l0 - mx);
  float a1 = (lane < 4) ? __expf(l1 - mx) : 0.0f;
  float sm = a0 + a1;
#pragma unroll
  for (int o = 16; o >= 1; o >>= 1)
    sm += __shfl_xor_sync(0xffffffffu, sm, o);
  float inv = 1.0f / sm;
  s_a[wid][lane] = a0 * inv;
  if (lane < 4) s_a[wid][32 + lane] = a1 * inv;
  __syncwarp();

  float vacc[8] = {};
#pragma unroll
  for (int it = 0; it < 18; it++) {
    int p = it * 2 + half16;
    int j = ip[p];                                // element offset
    __half ah = __float2half_rn(s_a[wid][p]);
    unsigned short au = __half_as_ushort(ah);
    uint4 v = *(const uint4*)&vb[j + s16 * 8];
    unsigned short v0, v1;
    unpack2(v0, v1, v.x); fmah(vacc[0], v0, au); fmah(vacc[1], v1, au);
    unpack2(v0, v1, v.y); fmah(vacc[2], v0, au); fmah(vacc[3], v1, au);
    unpack2(v0, v1, v.z); fmah(vacc[4], v0, au); fmah(vacc[5], v1, au);
    unpack2(v0, v1, v.w); fmah(vacc[6], v0, au); fmah(vacc[7], v1, au);
  }
#pragma unroll
  for (int d = 0; d < 8; d++)
    vacc[d] += __shfl_xor_sync(0xffffffffu, vacc[d], 16);

  if (half16 == 0) {
    __nv_bfloat16 hh[8], ll[8];
#pragma unroll
    for (int i = 0; i < 8; i++) {
      hh[i] = __float2bfloat16(vacc[i]);
      ll[i] = __float2bfloat16(vacc[i] - __bfloat162float(hh[i]));
    }
    size_t base = (size_t)token * D1 + h * EMB + s16 * 8;
    *(uint4*)&g_aoh[base] = *(uint4*)hh;
    *(uint4*)&g_aol[base] = *(uint4*)ll;
  }
}

// ---------------- Kernel 4: output GEMM (64x128 tile, split-K x8) -----------
__global__ __launch_bounds__(256) void out_gemm() {
  extern __shared__ __nv_bfloat16 dsm[];
  __nv_bfloat16* sAh = dsm;
  __nv_bfloat16* sAl = dsm + 2 * ASTG;
  __nv_bfloat16* sBh = dsm + 4 * ASTG;
  __nv_bfloat16* sBl = dsm + 4 * ASTG + 2 * BSTG;
  int bm = blockIdx.x, kslice = blockIdx.y;
  int tid = threadIdx.x, wid = tid >> 5, lane = tid & 31;
  int wm = wid >> 2, wn = wid & 3;     // 2 x 4 warps, warp tile 32x32
  float acc[2][4][4] = {};
  int kbase = kslice * 128;

  int rA = tid >> 2, cA = tid & 3;                 // 64 rows x 4 chunks
  int rB0 = tid >> 2, cB0 = tid & 3;               // 128 rows x 4 chunks
  int rB1 = (tid + 256) >> 2, cB1 = (tid + 256) & 3;

  auto load_stage = [&](int st, int kc) {
    int soA = st * ASTG + rA * SPAD + cA * 8;
    int soB0 = st * BSTG + rB0 * SPAD + cB0 * 8;
    int soB1 = st * BSTG + rB1 * SPAD + cB1 * 8;
    size_t ga = (size_t)(bm * 64 + rA) * D1 + kc + cA * 8;
    size_t gb0 = (size_t)rB0 * D1 + kc + cB0 * 8;
    size_t gb1 = (size_t)rB1 * D1 + kc + cB1 * 8;
    cpa16(&sAh[soA], &g_aoh[ga]);
    cpa16(&sAl[soA], &g_aol[ga]);
    cpa16(&sBh[soB0], &g_Wuth[gb0]); cpa16(&sBh[soB1], &g_Wuth[gb1]);
    cpa16(&sBl[soB0], &g_Wutl[gb0]); cpa16(&sBl[soB1], &g_Wutl[gb1]);
    CP_COMMIT();
  };

  load_stage(0, kbase);
#pragma unroll
  for (int kci = 0; kci < 4; kci++) {
    if (kci < 3) load_stage((kci + 1) & 1, kbase + (kci + 1) * 32);
    if (kci < 3) { CP_WAIT1(); } else { CP_WAIT0(); }
    __syncthreads();
    __nv_bfloat16* pAh = sAh + (kci & 1) * ASTG;
    __nv_bfloat16* pAl = sAl + (kci & 1) * ASTG;
    __nv_bfloat16* pBh = sBh + (kci & 1) * BSTG;
    __nv_bfloat16* pBl = sBl + (kci & 1) * BSTG;
#pragma unroll
    for (int ks = 0; ks < 32; ks += 16) {
      uint32_t Ah[2][4], Al[2][4], Bh[2][4], Bl[2][4];
#pragma unroll
      for (int mt = 0; mt < 2; mt++) {
        int off = (wm * 32 + mt * 16 + (lane & 15)) * SPAD + ks + 8 * (lane >> 4);
        ldsm4(Ah[mt], &pAh[off]);
        ldsm4(Al[mt], &pAl[off]);
      }
#pragma unroll
      for (int nb = 0; nb < 2; nb++) {
        int off = (wn * 32 + nb * 16 + 8 * ((lane >> 4) & 1) + (lane & 7)) * SPAD
                  + ks + 8 * ((lane >> 3) & 1);
        ldsm4(Bh[nb], &pBh[off]);
        ldsm4(Bl[nb], &pBl[off]);
      }
#pragma unroll
      for (int mt = 0; mt < 2; mt++)
#pragma unroll
        for (int nb = 0; nb < 2; nb++) {
          mma16816(acc[mt][nb * 2],     Ah[mt], &Bh[nb][0]);
          mma16816(acc[mt][nb * 2],     Ah[mt], &Bl[nb][0]);
          mma16816(acc[mt][nb * 2],     Al[mt], &Bh[nb][0]);
          mma16816(acc[mt][nb * 2 + 1], Ah[mt], &Bh[nb][2]);
          mma16816(acc[mt][nb * 2 + 1], Ah[mt], &Bl[nb][2]);
          mma16816(acc[mt][nb * 2 + 1], Al[mt], &Bh[nb][2]);
        }
    }
    __syncthreads();
  }

  int g = lane >> 2, t = lane & 3;
  float* dst = g_part[kslice];
#pragma unroll
  for (int mt = 0; mt < 2; mt++)
#pragma unroll
    for (int nt = 0; nt < 4; nt++) {
      int row = bm * 64 + wm * 32 + mt * 16 + g;
      int col = wn * 32 + nt * 8 + 2 * t;
      *(float2*)&dst[(size_t)row * 128 + col] =
          make_float2(acc[mt][nt][0], acc[mt][nt][1]);
      *(float2*)&dst[(size_t)(row + 8) * 128 + col] =
          make_float2(acc[mt][nt][2], acc[mt][nt][3]);
    }
}

// Deterministic reduce of the 8 split-K partials + bias.
__global__ __launch_bounds__(256) void out_reduce(float* __restrict__ Cout,
                                                  const float* __restrict__ bu) {
  int e4 = blockIdx.x * 256 + threadIdx.x;   // float4 index, 0..131071
  int col0 = (e4 * 4) & 127;
  float4 s = *(const float4*)(bu + col0);
#pragma unroll
  for (int ks = 0; ks < 8; ks++) {
    float4 p = *(const float4*)(g_part[ks] + e4 * 4);
    s.x += p.x; s.y += p.y; s.z += p.z; s.w += p.w;
  }
  *(float4*)(Cout + e4 * 4) = s;
}

// ---------------- launch ----------------------------------------------------
extern "C" void kernel_launch(void* const* d_in, const int* in_sizes, int n_in,
                              void* d_out, int out_size) {
  const float* x   = (const float*)d_in[0];
  const float* sp  = (const float*)d_in[1];
  const float* mv  = (const float*)d_in[2];
  const float* Wq  = (const float*)d_in[3];
  const float* Wk  = (const float*)d_in[4];
  const float* Wv  = (const float*)d_in[5];
  const float* Wu  = (const float*)d_in[6];
  const float* bu  = (const float*)d_in[7];
  float* out = (float*)d_out;

  static bool attr_done = false;
  if (!attr_done) {
    cudaFuncSetAttribute(qkv_gemm, cudaFuncAttributeMaxDynamicSharedMemorySize, DSMEM);
    cudaFuncSetAttribute(out_gemm, cudaFuncAttributeMaxDynamicSharedMemorySize, DSMEM2);
    attr_done = true;
  }

  prepass<<<2048, 256>>>(x, Wq, Wk, Wv, Wu, sp, mv);
  qkv_gemm<<<dim3(24, 32), 256, DSMEM>>>();
  attn_kernel<<<dim3(256, 8), 512>>>();
  out_gemm<<<dim3(64, 8), 256, DSMEM2>>>();
  out_reduce<<<512, 256>>>(out, bu);
}

// round 14
// speedup vs baseline: 1.0283x; 1.0244x over previous
#include <cuda_runtime.h>
#include <cuda_bf16.h>
#include <cuda_fp16.h>
#include <stdint.h>
#include <math.h>

// Problem constants
#define Tn    2048
#define EMB   128
#define NH    8
#define Mv    9      // M
#define Pp    36     // P
#define BT    4096   // B*T
#define D1    1024   // NH*EMB
#define D3    3072   // 3*D1
#define SPAD  40     // padded bf16 smem row stride (80B: ldmatrix conflict-free)
#define STG   (128 * SPAD)            // qkv: elems per stage per array
#define DSMEM (8 * STG * 2)           // qkv: bytes
#define ASTG  (64 * SPAD)             // out: A elems per stage per array
#define BSTG  (128 * SPAD)            // out: B elems per stage per array
#define DSMEM2 ((4 * ASTG + 4 * BSTG) * 2)  // out: bytes (61440)

// Scratch (static device arrays; no allocation allowed)
__device__ __half g_q[BT * D1];            // Q fp16 (scaled), token-major
__device__ __half g_K[2 * NH * Tn * EMB];  // K fp16 (scaled), [b][h][t][d]
__device__ __half g_V[2 * NH * Tn * EMB];  // V fp16,          [b][h][t][d]
__device__ int   g_idx[BT * Pp];           // element offsets (j*EMB)
__device__ float g_w[BT * Pp];
__device__ float g_part[4][BT * 128];      // split-K partials for out gemm

// pre-split bf16 hi/lo operands
__device__ __nv_bfloat16 g_Xh[BT * EMB],  g_Xl[BT * EMB];     // X
__device__ __nv_bfloat16 g_Wth[D3 * EMB], g_Wtl[D3 * EMB];    // [Wq|Wk|Wv]^T [n][k]
__device__ __nv_bfloat16 g_Wuth[EMB * D1], g_Wutl[EMB * D1];  // Wu^T [128][1024]
__device__ __nv_bfloat16 g_aoh[BT * D1], g_aol[BT * D1];      // attn out hi/lo

// ---------------- threefry-2x32 (JAX-compatible, 20 rounds) ----------------
__device__ __forceinline__ void tf2x32(uint32_t k0, uint32_t k1,
                                       uint32_t& x0, uint32_t& x1) {
  uint32_t ks2 = k0 ^ k1 ^ 0x1BD11BDAu;
  x0 += k0; x1 += k1;
#define TFR(r) { x0 += x1; x1 = (x1 << (r)) | (x1 >> (32 - (r))); x1 ^= x0; }
  TFR(13) TFR(15) TFR(26) TFR(6)
  x0 += k1;  x1 += ks2 + 1u;
  TFR(17) TFR(29) TFR(16) TFR(24)
  x0 += ks2; x1 += k0 + 2u;
  TFR(13) TFR(15) TFR(26) TFR(6)
  x0 += k0;  x1 += k1 + 3u;
  TFR(17) TFR(29) TFR(16) TFR(24)
  x0 += k1;  x1 += ks2 + 4u;
  TFR(13) TFR(15) TFR(26) TFR(6)
  x0 += ks2; x1 += k0 + 5u;
#undef TFR
}

// ---------------- MMA / ldmatrix / cp.async helpers -------------------------
__device__ __forceinline__ void mma16816(float* c, const uint32_t* a, const uint32_t* b) {
  asm volatile(
    "mma.sync.aligned.m16n8k16.row.col.f32.bf16.bf16.f32 "
    "{%0,%1,%2,%3}, {%4,%5,%6,%7}, {%8,%9}, {%0,%1,%2,%3};"
    : "+f"(c[0]), "+f"(c[1]), "+f"(c[2]), "+f"(c[3])
    : "r"(a[0]), "r"(a[1]), "r"(a[2]), "r"(a[3]), "r"(b[0]), "r"(b[1]));
}
__device__ __forceinline__ void ldsm4(uint32_t* r, const __nv_bfloat16* p) {
  uint32_t a = (uint32_t)__cvta_generic_to_shared(p);
  asm volatile("ldmatrix.sync.aligned.m8n8.x4.shared.b16 {%0,%1,%2,%3}, [%4];"
               : "=r"(r[0]), "=r"(r[1]), "=r"(r[2]), "=r"(r[3]) : "r"(a));
}
__device__ __forceinline__ void cpa16(__nv_bfloat16* dst, const __nv_bfloat16* src) {
  uint32_t d = (uint32_t)__cvta_generic_to_shared(dst);
  asm volatile("cp.async.ca.shared.global [%0], [%1], 16;" :: "r"(d), "l"(src));
}
#define CP_COMMIT() asm volatile("cp.async.commit_group;")
#define CP_WAIT1()  asm volatile("cp.async.wait_group 1;" ::: "memory")
#define CP_WAIT0()  asm volatile("cp.async.wait_group 0;" ::: "memory")

// mixed-precision fma: f16 inputs, f32 accumulate (PTX ISA 8.6, sm_100+)
__device__ __forceinline__ void fmah(float& acc, unsigned short a, unsigned short b) {
  asm("fma.rn.f32.f16 %0, %1, %2, %0;" : "+f"(acc) : "h"(a), "h"(b));
}
__device__ __forceinline__ void unpack2(unsigned short& h0, unsigned short& h1, uint32_t w) {
  asm("mov.b32 {%0, %1}, %2;" : "=h"(h0), "=h"(h1) : "r"(w));
}
__device__ __forceinline__ float dot8h(uint4 q, uint4 k) {
  unsigned short qa, qb, ka, kb;
  float a0 = 0.f, a1 = 0.f;
  unpack2(qa, qb, q.x); unpack2(ka, kb, k.x);
  fmah(a0, qa, ka); fmah(a1, qb, kb);
  unpack2(qa, qb, q.y); unpack2(ka, kb, k.y);
  fmah(a0, qa, ka); fmah(a1, qb, kb);
  unpack2(qa, qb, q.z); unpack2(ka, kb, k.z);
  fmah(a0, qa, ka); fmah(a1, qb, kb);
  unpack2(qa, qb, q.w); unpack2(ka, kb, k.w);
  fmah(a0, qa, ka); fmah(a1, qb, kb);
  return a0 + a1;
}

// ---------------- Prepass A: split X + transpose/split weights --------------
__device__ void twsplit_body(const float* __restrict__ src,
                             __nv_bfloat16* __restrict__ dh,
                             __nv_bfloat16* __restrict__ dl,
                             int N, int Kd, int nofs, int bx, int by,
                             float* tile /*32x33*/) {
  int tx = threadIdx.x & 31, ty = threadIdx.x >> 5;   // 32 x 8
  int n0 = bx * 32, k0 = by * 32;
  for (int i = ty; i < 32; i += 8)
    tile[i * 33 + tx] = src[(size_t)(k0 + i) * N + n0 + tx];
  __syncthreads();
  for (int i = ty; i < 32; i += 8) {
    float v = tile[tx * 33 + i];                 // src[k0+tx][n0+i]
    __nv_bfloat16 h = __float2bfloat16(v);
    __nv_bfloat16 l = __float2bfloat16(v - __bfloat162float(h));
    size_t o = (size_t)(nofs + n0 + i) * Kd + k0 + tx;
    dh[o] = h; dl[o] = l;
  }
}

__global__ __launch_bounds__(256) void prepass_xw(const float* __restrict__ X,
                                                  const float* __restrict__ Wq,
                                                  const float* __restrict__ Wk,
                                                  const float* __restrict__ Wv,
                                                  const float* __restrict__ Wu) {
  __shared__ float tile[32 * 33];
  int bid = blockIdx.x;
  if (bid < 512) {                      // split X
    int e4 = bid * 256 + threadIdx.x;
    float4 v = *(const float4*)(X + e4 * 4);
    float f[4] = {v.x, v.y, v.z, v.w};
    __nv_bfloat16 h[4], l[4];
#pragma unroll
    for (int i = 0; i < 4; i++) {
      h[i] = __float2bfloat16(f[i]);
      l[i] = __float2bfloat16(f[i] - __bfloat162float(h[i]));
    }
    *(uint2*)&g_Xh[e4 * 4] = *(uint2*)h;
    *(uint2*)&g_Xl[e4 * 4] = *(uint2*)l;
  } else {
    int r = bid - 512;                  // 0..511
    int which = r >> 7, sub = r & 127;
    if (which < 3) {                    // Wq/Wk/Wv
      const float* src = (which == 0) ? Wq : ((which == 1) ? Wk : Wv);
      twsplit_body(src, g_Wth, g_Wtl, 1024, 128, which * 1024,
                   sub & 31, sub >> 5, tile);
    } else {                            // Wu
      twsplit_body(Wu, g_Wuth, g_Wutl, 128, 1024, 0,
                   sub & 3, sub >> 2, tile);
    }
  }
}

// ---------------- Prepass B: indices + weights (runs on side stream) -------
__global__ __launch_bounds__(256) void idxw_kernel(const float* __restrict__ sp,
                                                   const float* __restrict__ mvals) {
  int sub = threadIdx.x >> 6;          // 0..3 (4 tokens per 256-thr block)
  int p = threadIdx.x & 63;
  int token = blockIdx.x * 4 + sub;    // 0..4095
  int b = token >> 11, t = token & 2047;
  __shared__ float s_mean[4][Mv];
  __shared__ float s_sigma_inv;
  __shared__ int   s_idx[4][Pp];
  __shared__ float s_ptsfl[4][Pp];
  __shared__ float s_dens[4][Pp][Mv];
  __shared__ float s_colinv[4][Mv];

  float dil = sp[0];
  if (p < Mv) {
    float off = __fmul_rn((float)(p - 4), dil);
    float mu  = __fadd_rn((float)t, off);
    mu = fminf(fmaxf(mu, 0.0f), (float)(Tn - 1));
    s_mean[sub][p] = mu;
  }
  if (threadIdx.x == 0) {
    float s = sp[1] + 2.0f;                 // SIGMA_BOOST
    float sigma = log1pf(expf(s)) + 1e-7f;  // softplus + EPS
    s_sigma_inv = 1.0f / sigma;
  }
  __syncthreads();

  if (p < Pp) {
    int m = p >> 2, slot = p & 3;
    float fl = floorf(s_mean[sub][m]);
    float val;
    if (slot == 0) val = fl;
    else if (slot == 1) val = fl + 1.0f;
    else {
      // JAX partitionable threefry (verified in R2)
      uint32_t k2a = 0u, k2b = 1u;
      tf2x32(0u, 42u, k2a, k2b);
      uint32_t i = (uint32_t)(b * 36864 + t * 18 + m * 2 + (slot - 2));
      uint32_t x0 = 0u, x1 = i;
      tf2x32(k2a, k2b, x0, x1);
      uint32_t bits = x0 ^ x1;
      val = (float)(bits & 2047u);
    }
    val = fminf(fmaxf(val, 0.0f), (float)(Tn - 1));
    int iv = (int)val;
    s_idx[sub][p] = iv;
    s_ptsfl[sub][p] = (float)iv;
  }
  __syncthreads();

  if (p < Pp) {
    bool dup = false;
    int my = s_idx[sub][p];
    for (int q = 0; q < p; q++) dup |= (s_idx[sub][q] == my);
    float inv_s = s_sigma_inv;
#pragma unroll
    for (int m = 0; m < Mv; m++) {
      float d = (s_ptsfl[sub][p] - s_mean[sub][m]) * inv_s;
      s_dens[sub][p][m] = dup ? 0.0f : expf(-0.5f * d * d);
    }
  }
  __syncthreads();

  if (p < Mv) {
    float sum = 0.0f;
    for (int q = 0; q < Pp; q++) sum += s_dens[sub][q][p];
    s_colinv[sub][p] = 1.0f / sum;
  }
  __syncthreads();

  if (p < Pp) {
    float w = 0.0f;
#pragma unroll
    for (int m = 0; m < Mv; m++) w += s_dens[sub][p][m] * s_colinv[sub][m] * mvals[m];
    g_idx[token * Pp + p] = s_idx[sub][p] * EMB;   // element offset for attn
    g_w[token * Pp + p] = w;
  }
}

// ---------------- shared GEMM inner machinery (128-row variant) -------------
__device__ __forceinline__ void gemm_mma_stage(
    __nv_bfloat16* sAh, __nv_bfloat16* sAl,
    __nv_bfloat16* sBh, __nv_bfloat16* sBl,
    int wm, int wn, int lane, float acc[2][8][4]) {
#pragma unroll
  for (int ks = 0; ks < 32; ks += 16) {
    uint32_t Ah[2][4], Al[2][4], Bh[4][4], Bl[4][4];
#pragma unroll
    for (int mt = 0; mt < 2; mt++) {
      int off = (wm * 32 + mt * 16 + (lane & 15)) * SPAD + ks + 8 * (lane >> 4);
      ldsm4(Ah[mt], &sAh[off]);
      ldsm4(Al[mt], &sAl[off]);
    }
#pragma unroll
    for (int nb = 0; nb < 4; nb++) {
      int off = (wn * 64 + nb * 16 + 8 * ((lane >> 4) & 1) + (lane & 7)) * SPAD
                + ks + 8 * ((lane >> 3) & 1);
      ldsm4(Bh[nb], &sBh[off]);
      ldsm4(Bl[nb], &sBl[off]);
    }
#pragma unroll
    for (int mt = 0; mt < 2; mt++)
#pragma unroll
      for (int nb = 0; nb < 4; nb++) {
        mma16816(acc[mt][nb * 2],     Ah[mt], &Bh[nb][0]);
        mma16816(acc[mt][nb * 2],     Ah[mt], &Bl[nb][0]);
        mma16816(acc[mt][nb * 2],     Al[mt], &Bh[nb][0]);
        mma16816(acc[mt][nb * 2 + 1], Ah[mt], &Bh[nb][2]);
        mma16816(acc[mt][nb * 2 + 1], Ah[mt], &Bl[nb][2]);
        mma16816(acc[mt][nb * 2 + 1], Al[mt], &Bh[nb][2]);
      }
  }
}

// ---------------- Kernel 1: fused QKV projection (tensor core, pipelined) --
__global__ __launch_bounds__(256) void qkv_gemm() {
  extern __shared__ __nv_bfloat16 dsm[];
  __nv_bfloat16* sAh = dsm;
  __nv_bfloat16* sAl = dsm + 2 * STG;
  __nv_bfloat16* sBh = dsm + 4 * STG;
  __nv_bfloat16* sBl = dsm + 6 * STG;
  int bn = blockIdx.x, bm = blockIdx.y;
  int n_glob0 = bn * 128;
  int tid = threadIdx.x, wid = tid >> 5, lane = tid & 31;
  int wm = wid >> 1, wn = wid & 1;
  float acc[2][8][4] = {};

  int r0 = tid >> 2, c0 = tid & 3;
  int r1 = (tid + 256) >> 2, c1 = (tid + 256) & 3;

  auto load_stage = [&](int st, int kc) {
    int so0 = st * STG + r0 * SPAD + c0 * 8;
    int so1 = st * STG + r1 * SPAD + c1 * 8;
    size_t ga0 = (size_t)(bm * 128 + r0) * 128 + kc + c0 * 8;
    size_t ga1 = (size_t)(bm * 128 + r1) * 128 + kc + c1 * 8;
    size_t gb0 = (size_t)(n_glob0 + r0) * 128 + kc + c0 * 8;
    size_t gb1 = (size_t)(n_glob0 + r1) * 128 + kc + c1 * 8;
    cpa16(&sAh[so0], &g_Xh[ga0]);  cpa16(&sAh[so1], &g_Xh[ga1]);
    cpa16(&sAl[so0], &g_Xl[ga0]);  cpa16(&sAl[so1], &g_Xl[ga1]);
    cpa16(&sBh[so0], &g_Wth[gb0]); cpa16(&sBh[so1], &g_Wth[gb1]);
    cpa16(&sBl[so0], &g_Wtl[gb0]); cpa16(&sBl[so1], &g_Wtl[gb1]);
    CP_COMMIT();
  };

  load_stage(0, 0);
#pragma unroll
  for (int kci = 0; kci < 4; kci++) {
    if (kci < 3) load_stage((kci + 1) & 1, (kci + 1) * 32);
    if (kci < 3) { CP_WAIT1(); } else { CP_WAIT0(); }
    __syncthreads();
    int st = (kci & 1) * STG;
    gemm_mma_stage(sAh + st, sAl + st, sBh + st, sBl + st, wm, wn, lane, acc);
    __syncthreads();
  }

  int g = lane >> 2, t = lane & 3;
  int seg = n_glob0 >> 10;                          // 0=Q 1=K 2=V
  float scale = (seg < 2) ? 0.29730177875068026f : 1.0f; // 1/128^0.25
#pragma unroll
  for (int mt = 0; mt < 2; mt++)
#pragma unroll
    for (int nt = 0; nt < 8; nt++) {
      int row = bm * 128 + wm * 32 + mt * 16 + g;
      int col = n_glob0 + wn * 64 + nt * 8 + 2 * t;
      float2 v0 = make_float2(acc[mt][nt][0] * scale, acc[mt][nt][1] * scale);
      float2 v1 = make_float2(acc[mt][nt][2] * scale, acc[mt][nt][3] * scale);
      if (seg == 0) {
        *(__half2*)&g_q[(size_t)row * D1 + col] = __float22half2_rn(v0);
        *(__half2*)&g_q[(size_t)(row + 8) * D1 + col] = __float22half2_rn(v1);
      } else {
        int c = col & 1023, h = c >> 7, d = c & 127;
        int b = row >> 11, tt = row & 2047;
        __half* dst = (seg == 1) ? g_K : g_V;
        size_t base = ((size_t)(b * NH + h) * Tn + tt) * EMB + d;
        *(__half2*)&dst[base] = __float22half2_rn(v0);
        *(__half2*)&dst[base + 8 * EMB] = __float22half2_rn(v1);
      }
    }
}

// ---------------- Kernel 3: gathered attention (fp16 math, f32 accum) ------
__global__ __launch_bounds__(512) void attn_kernel() {
  __shared__ float s_logit[16][Pp];
  __shared__ float s_a[16][Pp];
  int tid = threadIdx.x;
  int wid = tid >> 5, lane = tid & 31;
  int g = lane >> 3, sub = lane & 7;       // QK: 4 groups x 8 lanes
  int half16 = lane >> 4, s16 = lane & 15; // V: 2 halves x 16 lanes
  int token = blockIdx.x * 16 + wid;
  int h = blockIdx.y;
  int b = token >> 11;

  const __half* qp = g_q + (size_t)token * D1 + h * EMB;
  const int*   ip = g_idx + token * Pp;
  const float* wp = g_w + token * Pp;
  const __half* kb = g_K + (size_t)(b * NH + h) * Tn * EMB;
  const __half* vb = g_V + (size_t)(b * NH + h) * Tn * EMB;

  uint4 q0 = *(const uint4*)&qp[sub * 8];        // 8 fp16
  uint4 q1 = *(const uint4*)&qp[64 + sub * 8];   // 8 fp16

#pragma unroll
  for (int it = 0; it < 9; it++) {
    int p = it * 4 + g;
    int j = ip[p];                                // element offset (j*EMB)
    const __half* kr = kb + j;
    uint4 k0 = *(const uint4*)&kr[sub * 8];
    uint4 k1 = *(const uint4*)&kr[64 + sub * 8];
    float d = dot8h(q0, k0) + dot8h(q1, k1);
    d += __shfl_xor_sync(0xffffffffu, d, 4);
    d += __shfl_xor_sync(0xffffffffu, d, 2);
    d += __shfl_xor_sync(0xffffffffu, d, 1);
    if (sub == 0) s_logit[wid][p] = wp[p] * d;
  }
  __syncwarp();

  float l0 = s_logit[wid][lane];
  float l1 = (lane < 4) ? s_logit[wid][32 + lane] : -1e30f;
  float mx = fmaxf(l0, l1);
#pragma unroll
  for (int o = 16; o >= 1; o >>= 1)
    mx = fmaxf(mx, __shfl_xor_sync(0xffffffffu, mx, o));
  float a0 = __expf(l0 - mx);
  float a1 = (lane < 4) ? __expf(l1 - mx) : 0.0f;
  float sm = a0 + a1;
#pragma unroll
  for (int o = 16; o >= 1; o >>= 1)
    sm += __shfl_xor_sync(0xffffffffu, sm, o);
  float inv = 1.0f / sm;
  s_a[wid][lane] = a0 * inv;
  if (lane < 4) s_a[wid][32 + lane] = a1 * inv;
  __syncwarp();

  float vacc[8] = {};
#pragma unroll
  for (int it = 0; it < 18; it++) {
    int p = it * 2 + half16;
    int j = ip[p];                                // element offset
    __half ah = __float2half_rn(s_a[wid][p]);
    unsigned short au = __half_as_ushort(ah);
    uint4 v = *(const uint4*)&vb[j + s16 * 8];
    unsigned short v0, v1;
    unpack2(v0, v1, v.x); fmah(vacc[0], v0, au); fmah(vacc[1], v1, au);
    unpack2(v0, v1, v.y); fmah(vacc[2], v0, au); fmah(vacc[3], v1, au);
    unpack2(v0, v1, v.z); fmah(vacc[4], v0, au); fmah(vacc[5], v1, au);
    unpack2(v0, v1, v.w); fmah(vacc[6], v0, au); fmah(vacc[7], v1, au);
  }
#pragma unroll
  for (int d = 0; d < 8; d++)
    vacc[d] += __shfl_xor_sync(0xffffffffu, vacc[d], 16);

  if (half16 == 0) {
    __nv_bfloat16 hh[8], ll[8];
#pragma unroll
    for (int i = 0; i < 8; i++) {
      hh[i] = __float2bfloat16(vacc[i]);
      ll[i] = __float2bfloat16(vacc[i] - __bfloat162float(hh[i]));
    }
    size_t base = (size_t)token * D1 + h * EMB + s16 * 8;
    *(uint4*)&g_aoh[base] = *(uint4*)hh;
    *(uint4*)&g_aol[base] = *(uint4*)ll;
  }
}

// ---------------- Kernel 4: output GEMM (64x128 tile, split-K x4) -----------
__global__ __launch_bounds__(256) void out_gemm() {
  extern __shared__ __nv_bfloat16 dsm[];
  __nv_bfloat16* sAh = dsm;
  __nv_bfloat16* sAl = dsm + 2 * ASTG;
  __nv_bfloat16* sBh = dsm + 4 * ASTG;
  __nv_bfloat16* sBl = dsm + 4 * ASTG + 2 * BSTG;
  int bm = blockIdx.x, kslice = blockIdx.y;
  int tid = threadIdx.x, wid = tid >> 5, lane = tid & 31;
  int wm = wid >> 2, wn = wid & 3;     // 2 x 4 warps, warp tile 32x32
  float acc[2][4][4] = {};
  int kbase = kslice * 256;

  int rA = tid >> 2, cA = tid & 3;                 // 64 rows x 4 chunks
  int rB0 = tid >> 2, cB0 = tid & 3;               // 128 rows x 4 chunks
  int rB1 = (tid + 256) >> 2, cB1 = (tid + 256) & 3;

  auto load_stage = [&](int st, int kc) {
    int soA = st * ASTG + rA * SPAD + cA * 8;
    int soB0 = st * BSTG + rB0 * SPAD + cB0 * 8;
    int soB1 = st * BSTG + rB1 * SPAD + cB1 * 8;
    size_t ga = (size_t)(bm * 64 + rA) * D1 + kc + cA * 8;
    size_t gb0 = (size_t)rB0 * D1 + kc + cB0 * 8;
    size_t gb1 = (size_t)rB1 * D1 + kc + cB1 * 8;
    cpa16(&sAh[soA], &g_aoh[ga]);
    cpa16(&sAl[soA], &g_aol[ga]);
    cpa16(&sBh[soB0], &g_Wuth[gb0]); cpa16(&sBh[soB1], &g_Wuth[gb1]);
    cpa16(&sBl[soB0], &g_Wutl[gb0]); cpa16(&sBl[soB1], &g_Wutl[gb1]);
    CP_COMMIT();
  };

  load_stage(0, kbase);
#pragma unroll
  for (int kci = 0; kci < 8; kci++) {
    if (kci < 7) load_stage((kci + 1) & 1, kbase + (kci + 1) * 32);
    if (kci < 7) { CP_WAIT1(); } else { CP_WAIT0(); }
    __syncthreads();
    __nv_bfloat16* pAh = sAh + (kci & 1) * ASTG;
    __nv_bfloat16* pAl = sAl + (kci & 1) * ASTG;
    __nv_bfloat16* pBh = sBh + (kci & 1) * BSTG;
    __nv_bfloat16* pBl = sBl + (kci & 1) * BSTG;
#pragma unroll
    for (int ks = 0; ks < 32; ks += 16) {
      uint32_t Ah[2][4], Al[2][4], Bh[2][4], Bl[2][4];
#pragma unroll
      for (int mt = 0; mt < 2; mt++) {
        int off = (wm * 32 + mt * 16 + (lane & 15)) * SPAD + ks + 8 * (lane >> 4);
        ldsm4(Ah[mt], &pAh[off]);
        ldsm4(Al[mt], &pAl[off]);
      }
#pragma unroll
      for (int nb = 0; nb < 2; nb++) {
        int off = (wn * 32 + nb * 16 + 8 * ((lane >> 4) & 1) + (lane & 7)) * SPAD
                  + ks + 8 * ((lane >> 3) & 1);
        ldsm4(Bh[nb], &pBh[off]);
        ldsm4(Bl[nb], &pBl[off]);
      }
#pragma unroll
      for (int mt = 0; mt < 2; mt++)
#pragma unroll
        for (int nb = 0; nb < 2; nb++) {
          mma16816(acc[mt][nb * 2],     Ah[mt], &Bh[nb][0]);
          mma16816(acc[mt][nb * 2],     Ah[mt], &Bl[nb][0]);
          mma16816(acc[mt][nb * 2],     Al[mt], &Bh[nb][0]);
          mma16816(acc[mt][nb * 2 + 1], Ah[mt], &Bh[nb][2]);
          mma16816(acc[mt][nb * 2 + 1], Ah[mt], &Bl[nb][2]);
          mma16816(acc[mt][nb * 2 + 1], Al[mt], &Bh[nb][2]);
        }
    }
    __syncthreads();
  }

  int g = lane >> 2, t = lane & 3;
  float* dst = g_part[kslice];
#pragma unroll
  for (int mt = 0; mt < 2; mt++)
#pragma unroll
    for (int nt = 0; nt < 4; nt++) {
      int row = bm * 64 + wm * 32 + mt * 16 + g;
      int col = wn * 32 + nt * 8 + 2 * t;
      *(float2*)&dst[(size_t)row * 128 + col] =
          make_float2(acc[mt][nt][0], acc[mt][nt][1]);
      *(float2*)&dst[(size_t)(row + 8) * 128 + col] =
          make_float2(acc[mt][nt][2], acc[mt][nt][3]);
    }
}

// Deterministic reduce of the 4 split-K partials + bias.
__global__ __launch_bounds__(256) void out_reduce(float* __restrict__ Cout,
                                                  const float* __restrict__ bu) {
  int e4 = blockIdx.x * 256 + threadIdx.x;   // float4 index, 0..131071
  int col0 = (e4 * 4) & 127;
  float4 s = *(const float4*)(bu + col0);
#pragma unroll
  for (int ks = 0; ks < 4; ks++) {
    float4 p = *(const float4*)(g_part[ks] + e4 * 4);
    s.x += p.x; s.y += p.y; s.z += p.z; s.w += p.w;
  }
  *(float4*)(Cout + e4 * 4) = s;
}

// ---------------- launch ----------------------------------------------------
extern "C" void kernel_launch(void* const* d_in, const int* in_sizes, int n_in,
                              void* d_out, int out_size) {
  const float* x   = (const float*)d_in[0];
  const float* sp  = (const float*)d_in[1];
  const float* mv  = (const float*)d_in[2];
  const float* Wq  = (const float*)d_in[3];
  const float* Wk  = (const float*)d_in[4];
  const float* Wv  = (const float*)d_in[5];
  const float* Wu  = (const float*)d_in[6];
  const float* bu  = (const float*)d_in[7];
  float* out = (float*)d_out;

  static cudaStream_t s2 = nullptr;
  static cudaEvent_t evFork = nullptr, evJoin = nullptr;
  if (!s2) {   // first call = uncaptured correctness run: safe to create
    cudaStreamCreateWithFlags(&s2, cudaStreamNonBlocking);
    cudaEventCreateWithFlags(&evFork, cudaEventDisableTiming);
    cudaEventCreateWithFlags(&evJoin, cudaEventDisableTiming);
    cudaFuncSetAttribute(qkv_gemm, cudaFuncAttributeMaxDynamicSharedMemorySize, DSMEM);
    cudaFuncSetAttribute(out_gemm, cudaFuncAttributeMaxDynamicSharedMemorySize, DSMEM2);
  }

  // fork: idxw (attn-only dependency) runs concurrently with X/W split + qkv
  cudaEventRecord(evFork, 0);
  cudaStreamWaitEvent(s2, evFork, 0);
  idxw_kernel<<<1024, 256, 0, s2>>>(sp, mv);
  cudaEventRecord(evJoin, s2);

  prepass_xw<<<1024, 256>>>(x, Wq, Wk, Wv, Wu);
  qkv_gemm<<<dim3(24, 32), 256, DSMEM>>>();

  cudaStreamWaitEvent(0, evJoin, 0);   // join before attn consumes g_idx/g_w
  attn_kernel<<<dim3(256, 8), 512>>>();
  out_gemm<<<dim3(64, 4), 256, DSMEM2>>>();
  out_reduce<<<512, 256>>>(out, bu);
}

// round 15
// speedup vs baseline: 1.0384x; 1.0098x over previous
#include <cuda_runtime.h>
#include <cuda_bf16.h>
#include <cuda_fp16.h>
#include <stdint.h>
#include <math.h>

// Problem constants
#define Tn    2048
#define EMB   128
#define NH    8
#define Mv    9      // M
#define Pp    36     // P
#define BT    4096   // B*T
#define D1    1024   // NH*EMB
#define D3    3072   // 3*D1
#define SPAD  40     // padded bf16 smem row stride (80B: ldmatrix conflict-free)
#define STG   (128 * SPAD)            // qkv: elems per stage per array
#define DSMEM (8 * STG * 2)           // qkv: bytes
#define ASTG  (64 * SPAD)             // out: A elems per stage per array
#define BSTG  (128 * SPAD)            // out: B elems per stage per array
#define DSMEM2 ((4 * ASTG + 4 * BSTG) * 2)  // out: bytes (61440)

// Scratch (static device arrays; no allocation allowed)
__device__ __half g_q[BT * D1];            // Q fp16 (scaled), token-major
__device__ __half g_K[2 * NH * Tn * EMB];  // K fp16 (scaled), [b][h][t][d]
__device__ __half g_V[2 * NH * Tn * EMB];  // V fp16,          [b][h][t][d]
__device__ int   g_idx[BT * Pp];           // element offsets (j*EMB)
__device__ float g_w[BT * Pp];
__device__ float g_part[4][BT * 128];      // split-K partials for out gemm

// pre-split bf16 hi/lo operands
__device__ __nv_bfloat16 g_Xh[BT * EMB],  g_Xl[BT * EMB];     // X
__device__ __nv_bfloat16 g_Wth[D3 * EMB], g_Wtl[D3 * EMB];    // [Wq|Wk|Wv]^T [n][k]
__device__ __nv_bfloat16 g_Wuth[EMB * D1], g_Wutl[EMB * D1];  // Wu^T [128][1024]
__device__ __nv_bfloat16 g_aoh[BT * D1], g_aol[BT * D1];      // attn out hi/lo

// ---------------- threefry-2x32 (JAX-compatible, 20 rounds) ----------------
__device__ __forceinline__ void tf2x32(uint32_t k0, uint32_t k1,
                                       uint32_t& x0, uint32_t& x1) {
  uint32_t ks2 = k0 ^ k1 ^ 0x1BD11BDAu;
  x0 += k0; x1 += k1;
#define TFR(r) { x0 += x1; x1 = (x1 << (r)) | (x1 >> (32 - (r))); x1 ^= x0; }
  TFR(13) TFR(15) TFR(26) TFR(6)
  x0 += k1;  x1 += ks2 + 1u;
  TFR(17) TFR(29) TFR(16) TFR(24)
  x0 += ks2; x1 += k0 + 2u;
  TFR(13) TFR(15) TFR(26) TFR(6)
  x0 += k0;  x1 += k1 + 3u;
  TFR(17) TFR(29) TFR(16) TFR(24)
  x0 += k1;  x1 += ks2 + 4u;
  TFR(13) TFR(15) TFR(26) TFR(6)
  x0 += ks2; x1 += k0 + 5u;
#undef TFR
}

// ---------------- MMA / ldmatrix / cp.async helpers -------------------------
__device__ __forceinline__ void mma16816(float* c, const uint32_t* a, const uint32_t* b) {
  asm volatile(
    "mma.sync.aligned.m16n8k16.row.col.f32.bf16.bf16.f32 "
    "{%0,%1,%2,%3}, {%4,%5,%6,%7}, {%8,%9}, {%0,%1,%2,%3};"
    : "+f"(c[0]), "+f"(c[1]), "+f"(c[2]), "+f"(c[3])
    : "r"(a[0]), "r"(a[1]), "r"(a[2]), "r"(a[3]), "r"(b[0]), "r"(b[1]));
}
__device__ __forceinline__ void ldsm4(uint32_t* r, const __nv_bfloat16* p) {
  uint32_t a = (uint32_t)__cvta_generic_to_shared(p);
  asm volatile("ldmatrix.sync.aligned.m8n8.x4.shared.b16 {%0,%1,%2,%3}, [%4];"
               : "=r"(r[0]), "=r"(r[1]), "=r"(r[2]), "=r"(r[3]) : "r"(a));
}
__device__ __forceinline__ void cpa16(__nv_bfloat16* dst, const __nv_bfloat16* src) {
  uint32_t d = (uint32_t)__cvta_generic_to_shared(dst);
  asm volatile("cp.async.ca.shared.global [%0], [%1], 16;" :: "r"(d), "l"(src));
}
#define CP_COMMIT() asm volatile("cp.async.commit_group;")
#define CP_WAIT1()  asm volatile("cp.async.wait_group 1;" ::: "memory")
#define CP_WAIT0()  asm volatile("cp.async.wait_group 0;" ::: "memory")

// mixed-precision fma: f16 inputs, f32 accumulate (PTX ISA 8.6, sm_100+)
__device__ __forceinline__ void fmah(float& acc, unsigned short a, unsigned short b) {
  asm("fma.rn.f32.f16 %0, %1, %2, %0;" : "+f"(acc) : "h"(a), "h"(b));
}
__device__ __forceinline__ void unpack2(unsigned short& h0, unsigned short& h1, uint32_t w) {
  asm("mov.b32 {%0, %1}, %2;" : "=h"(h0), "=h"(h1) : "r"(w));
}
__device__ __forceinline__ float dot8h(uint4 q, uint4 k) {
  unsigned short qa, qb, ka, kb;
  float a0 = 0.f, a1 = 0.f;
  unpack2(qa, qb, q.x); unpack2(ka, kb, k.x);
  fmah(a0, qa, ka); fmah(a1, qb, kb);
  unpack2(qa, qb, q.y); unpack2(ka, kb, k.y);
  fmah(a0, qa, ka); fmah(a1, qb, kb);
  unpack2(qa, qb, q.z); unpack2(ka, kb, k.z);
  fmah(a0, qa, ka); fmah(a1, qb, kb);
  unpack2(qa, qb, q.w); unpack2(ka, kb, k.w);
  fmah(a0, qa, ka); fmah(a1, qb, kb);
  return a0 + a1;
}

// ---------------- Prepass A: split X + transpose/split weights --------------
__device__ void twsplit_body(const float* __restrict__ src,
                             __nv_bfloat16* __restrict__ dh,
                             __nv_bfloat16* __restrict__ dl,
                             int N, int Kd, int nofs, int bx, int by,
                             float* tile /*32x33*/) {
  int tx = threadIdx.x & 31, ty = threadIdx.x >> 5;   // 32 x 8
  int n0 = bx * 32, k0 = by * 32;
  for (int i = ty; i < 32; i += 8)
    tile[i * 33 + tx] = src[(size_t)(k0 + i) * N + n0 + tx];
  __syncthreads();
  for (int i = ty; i < 32; i += 8) {
    float v = tile[tx * 33 + i];                 // src[k0+tx][n0+i]
    __nv_bfloat16 h = __float2bfloat16(v);
    __nv_bfloat16 l = __float2bfloat16(v - __bfloat162float(h));
    size_t o = (size_t)(nofs + n0 + i) * Kd + k0 + tx;
    dh[o] = h; dl[o] = l;
  }
}

__global__ __launch_bounds__(256) void prepass_xw(const float* __restrict__ X,
                                                  const float* __restrict__ Wq,
                                                  const float* __restrict__ Wk,
                                                  const float* __restrict__ Wv,
                                                  const float* __restrict__ Wu) {
  __shared__ float tile[32 * 33];
  int bid = blockIdx.x;
  if (bid < 512) {                      // split X
    int e4 = bid * 256 + threadIdx.x;
    float4 v = *(const float4*)(X + e4 * 4);
    float f[4] = {v.x, v.y, v.z, v.w};
    __nv_bfloat16 h[4], l[4];
#pragma unroll
    for (int i = 0; i < 4; i++) {
      h[i] = __float2bfloat16(f[i]);
      l[i] = __float2bfloat16(f[i] - __bfloat162float(h[i]));
    }
    *(uint2*)&g_Xh[e4 * 4] = *(uint2*)h;
    *(uint2*)&g_Xl[e4 * 4] = *(uint2*)l;
  } else {
    int r = bid - 512;                  // 0..511
    int which = r >> 7, sub = r & 127;
    if (which < 3) {                    // Wq/Wk/Wv
      const float* src = (which == 0) ? Wq : ((which == 1) ? Wk : Wv);
      twsplit_body(src, g_Wth, g_Wtl, 1024, 128, which * 1024,
                   sub & 31, sub >> 5, tile);
    } else {                            // Wu
      twsplit_body(Wu, g_Wuth, g_Wutl, 128, 1024, 0,
                   sub & 3, sub >> 2, tile);
    }
  }
}

// ---------------- Prepass B: indices + weights (runs on side stream) -------
__global__ __launch_bounds__(256) void idxw_kernel(const float* __restrict__ sp,
                                                   const float* __restrict__ mvals) {
  int sub = threadIdx.x >> 6;          // 0..3 (4 tokens per 256-thr block)
  int p = threadIdx.x & 63;
  int token = blockIdx.x * 4 + sub;    // 0..4095
  int b = token >> 11, t = token & 2047;
  __shared__ float s_mean[4][Mv];
  __shared__ float s_sigma_inv;
  __shared__ int   s_idx[4][Pp];
  __shared__ float s_ptsfl[4][Pp];
  __shared__ float s_dens[4][Pp][Mv];
  __shared__ float s_colinv[4][Mv];

  float dil = sp[0];
  if (p < Mv) {
    float off = __fmul_rn((float)(p - 4), dil);
    float mu  = __fadd_rn((float)t, off);
    mu = fminf(fmaxf(mu, 0.0f), (float)(Tn - 1));
    s_mean[sub][p] = mu;
  }
  if (threadIdx.x == 0) {
    float s = sp[1] + 2.0f;                 // SIGMA_BOOST
    float sigma = log1pf(expf(s)) + 1e-7f;  // softplus + EPS
    s_sigma_inv = 1.0f / sigma;
  }
  __syncthreads();

  if (p < Pp) {
    int m = p >> 2, slot = p & 3;
    float fl = floorf(s_mean[sub][m]);
    float val;
    if (slot == 0) val = fl;
    else if (slot == 1) val = fl + 1.0f;
    else {
      // JAX partitionable threefry (verified in R2)
      uint32_t k2a = 0u, k2b = 1u;
      tf2x32(0u, 42u, k2a, k2b);
      uint32_t i = (uint32_t)(b * 36864 + t * 18 + m * 2 + (slot - 2));
      uint32_t x0 = 0u, x1 = i;
      tf2x32(k2a, k2b, x0, x1);
      uint32_t bits = x0 ^ x1;
      val = (float)(bits & 2047u);
    }
    val = fminf(fmaxf(val, 0.0f), (float)(Tn - 1));
    int iv = (int)val;
    s_idx[sub][p] = iv;
    s_ptsfl[sub][p] = (float)iv;
  }
  __syncthreads();

  if (p < Pp) {
    bool dup = false;
    int my = s_idx[sub][p];
    for (int q = 0; q < p; q++) dup |= (s_idx[sub][q] == my);
    float inv_s = s_sigma_inv;
#pragma unroll
    for (int m = 0; m < Mv; m++) {
      float d = (s_ptsfl[sub][p] - s_mean[sub][m]) * inv_s;
      s_dens[sub][p][m] = dup ? 0.0f : expf(-0.5f * d * d);
    }
  }
  __syncthreads();

  if (p < Mv) {
    float sum = 0.0f;
    for (int q = 0; q < Pp; q++) sum += s_dens[sub][q][p];
    s_colinv[sub][p] = 1.0f / sum;
  }
  __syncthreads();

  if (p < Pp) {
    float w = 0.0f;
#pragma unroll
    for (int m = 0; m < Mv; m++) w += s_dens[sub][p][m] * s_colinv[sub][m] * mvals[m];
    g_idx[token * Pp + p] = s_idx[sub][p] * EMB;   // element offset for attn
    g_w[token * Pp + p] = w;
  }
}

// ---------------- shared GEMM inner machinery (128-row variant) -------------
__device__ __forceinline__ void gemm_mma_stage(
    __nv_bfloat16* sAh, __nv_bfloat16* sAl,
    __nv_bfloat16* sBh, __nv_bfloat16* sBl,
    int wm, int wn, int lane, float acc[2][8][4]) {
#pragma unroll
  for (int ks = 0; ks < 32; ks += 16) {
    uint32_t Ah[2][4], Al[2][4], Bh[4][4], Bl[4][4];
#pragma unroll
    for (int mt = 0; mt < 2; mt++) {
      int off = (wm * 32 + mt * 16 + (lane & 15)) * SPAD + ks + 8 * (lane >> 4);
      ldsm4(Ah[mt], &sAh[off]);
      ldsm4(Al[mt], &sAl[off]);
    }
#pragma unroll
    for (int nb = 0; nb < 4; nb++) {
      int off = (wn * 64 + nb * 16 + 8 * ((lane >> 4) & 1) + (lane & 7)) * SPAD
                + ks + 8 * ((lane >> 3) & 1);
      ldsm4(Bh[nb], &sBh[off]);
      ldsm4(Bl[nb], &sBl[off]);
    }
#pragma unroll
    for (int mt = 0; mt < 2; mt++)
#pragma unroll
      for (int nb = 0; nb < 4; nb++) {
        mma16816(acc[mt][nb * 2],     Ah[mt], &Bh[nb][0]);
        mma16816(acc[mt][nb * 2],     Ah[mt], &Bl[nb][0]);
        mma16816(acc[mt][nb * 2],     Al[mt], &Bh[nb][0]);
        mma16816(acc[mt][nb * 2 + 1], Ah[mt], &Bh[nb][2]);
        mma16816(acc[mt][nb * 2 + 1], Ah[mt], &Bl[nb][2]);
        mma16816(acc[mt][nb * 2 + 1], Al[mt], &Bh[nb][2]);
      }
  }
}

// ---------------- Kernel 1: fused QKV projection (tensor core, pipelined) --
__global__ __launch_bounds__(256) void qkv_gemm() {
  extern __shared__ __nv_bfloat16 dsm[];
  __nv_bfloat16* sAh = dsm;
  __nv_bfloat16* sAl = dsm + 2 * STG;
  __nv_bfloat16* sBh = dsm + 4 * STG;
  __nv_bfloat16* sBl = dsm + 6 * STG;
  int bn = blockIdx.x, bm = blockIdx.y;
  int n_glob0 = bn * 128;
  int tid = threadIdx.x, wid = tid >> 5, lane = tid & 31;
  int wm = wid >> 1, wn = wid & 1;
  float acc[2][8][4] = {};

  int r0 = tid >> 2, c0 = tid & 3;
  int r1 = (tid + 256) >> 2, c1 = (tid + 256) & 3;

  auto load_stage = [&](int st, int kc) {
    int so0 = st * STG + r0 * SPAD + c0 * 8;
    int so1 = st * STG + r1 * SPAD + c1 * 8;
    size_t ga0 = (size_t)(bm * 128 + r0) * 128 + kc + c0 * 8;
    size_t ga1 = (size_t)(bm * 128 + r1) * 128 + kc + c1 * 8;
    size_t gb0 = (size_t)(n_glob0 + r0) * 128 + kc + c0 * 8;
    size_t gb1 = (size_t)(n_glob0 + r1) * 128 + kc + c1 * 8;
    cpa16(&sAh[so0], &g_Xh[ga0]);  cpa16(&sAh[so1], &g_Xh[ga1]);
    cpa16(&sAl[so0], &g_Xl[ga0]);  cpa16(&sAl[so1], &g_Xl[ga1]);
    cpa16(&sBh[so0], &g_Wth[gb0]); cpa16(&sBh[so1], &g_Wth[gb1]);
    cpa16(&sBl[so0], &g_Wtl[gb0]); cpa16(&sBl[so1], &g_Wtl[gb1]);
    CP_COMMIT();
  };

  load_stage(0, 0);
#pragma unroll
  for (int kci = 0; kci < 4; kci++) {
    if (kci < 3) load_stage((kci + 1) & 1, (kci + 1) * 32);
    if (kci < 3) { CP_WAIT1(); } else { CP_WAIT0(); }
    __syncthreads();
    int st = (kci & 1) * STG;
    gemm_mma_stage(sAh + st, sAl + st, sBh + st, sBl + st, wm, wn, lane, acc);
    __syncthreads();
  }

  int g = lane >> 2, t = lane & 3;
  int seg = n_glob0 >> 10;                          // 0=Q 1=K 2=V
  float scale = (seg < 2) ? 0.29730177875068026f : 1.0f; // 1/128^0.25
#pragma unroll
  for (int mt = 0; mt < 2; mt++)
#pragma unroll
    for (int nt = 0; nt < 8; nt++) {
      int row = bm * 128 + wm * 32 + mt * 16 + g;
      int col = n_glob0 + wn * 64 + nt * 8 + 2 * t;
      float2 v0 = make_float2(acc[mt][nt][0] * scale, acc[mt][nt][1] * scale);
      float2 v1 = make_float2(acc[mt][nt][2] * scale, acc[mt][nt][3] * scale);
      if (seg == 0) {
        *(__half2*)&g_q[(size_t)row * D1 + col] = __float22half2_rn(v0);
        *(__half2*)&g_q[(size_t)(row + 8) * D1 + col] = __float22half2_rn(v1);
      } else {
        int c = col & 1023, h = c >> 7, d = c & 127;
        int b = row >> 11, tt = row & 2047;
        __half* dst = (seg == 1) ? g_K : g_V;
        size_t base = ((size_t)(b * NH + h) * Tn + tt) * EMB + d;
        *(__half2*)&dst[base] = __float22half2_rn(v0);
        *(__half2*)&dst[base + 8 * EMB] = __float22half2_rn(v1);
      }
    }
}

// ---------------- Kernel 3: gathered attention (256-thr CTA, fp16 probs) ---
__global__ __launch_bounds__(256) void attn_kernel() {
  __shared__ float s_logit[8][Pp];
  __shared__ unsigned short s_a[8][Pp];   // probs as fp16 bits
  int tid = threadIdx.x;
  int wid = tid >> 5, lane = tid & 31;
  int g = lane >> 3, sub = lane & 7;       // QK: 4 groups x 8 lanes
  int half16 = lane >> 4, s16 = lane & 15; // V: 2 halves x 16 lanes
  int token = blockIdx.x * 8 + wid;
  int h = blockIdx.y;
  int b = token >> 11;

  const __half* qp = g_q + (size_t)token * D1 + h * EMB;
  const int*   ip = g_idx + token * Pp;
  const float* wp = g_w + token * Pp;
  const __half* kb = g_K + (size_t)(b * NH + h) * Tn * EMB;
  const __half* vb = g_V + (size_t)(b * NH + h) * Tn * EMB;

  uint4 q0 = *(const uint4*)&qp[sub * 8];        // 8 fp16
  uint4 q1 = *(const uint4*)&qp[64 + sub * 8];   // 8 fp16

#pragma unroll
  for (int it = 0; it < 9; it++) {
    int p = it * 4 + g;
    int j = ip[p];                                // element offset (j*EMB)
    const __half* kr = kb + j;
    uint4 k0 = *(const uint4*)&kr[sub * 8];
    uint4 k1 = *(const uint4*)&kr[64 + sub * 8];
    float d = dot8h(q0, k0) + dot8h(q1, k1);
    d += __shfl_xor_sync(0xffffffffu, d, 4);
    d += __shfl_xor_sync(0xffffffffu, d, 2);
    d += __shfl_xor_sync(0xffffffffu, d, 1);
    if (sub == 0) s_logit[wid][p] = wp[p] * d;
  }
  __syncwarp();

  float l0 = s_logit[wid][lane];
  float l1 = (lane < 4) ? s_logit[wid][32 + lane] : -1e30f;
  float mx = fmaxf(l0, l1);
#pragma unroll
  for (int o = 16; o >= 1; o >>= 1)
    mx = fmaxf(mx, __shfl_xor_sync(0xffffffffu, mx, o));
  float a0 = __expf(l0 - mx);
  float a1 = (lane < 4) ? __expf(l1 - mx) : 0.0f;
  float sm = a0 + a1;
#pragma unroll
  for (int o = 16; o >= 1; o >>= 1)
    sm += __shfl_xor_sync(0xffffffffu, sm, o);
  float inv = 1.0f / sm;
  s_a[wid][lane] = __half_as_ushort(__float2half_rn(a0 * inv));
  if (lane < 4) s_a[wid][32 + lane] = __half_as_ushort(__float2half_rn(a1 * inv));
  __syncwarp();

  float vacc[8] = {};
#pragma unroll
  for (int it = 0; it < 18; it++) {
    int p = it * 2 + half16;
    int j = ip[p];                                // element offset
    unsigned short au = s_a[wid][p];
    uint4 v = *(const uint4*)&vb[j + s16 * 8];
    unsigned short v0, v1;
    unpack2(v0, v1, v.x); fmah(vacc[0], v0, au); fmah(vacc[1], v1, au);
    unpack2(v0, v1, v.y); fmah(vacc[2], v0, au); fmah(vacc[3], v1, au);
    unpack2(v0, v1, v.z); fmah(vacc[4], v0, au); fmah(vacc[5], v1, au);
    unpack2(v0, v1, v.w); fmah(vacc[6], v0, au); fmah(vacc[7], v1, au);
  }
#pragma unroll
  for (int d = 0; d < 8; d++)
    vacc[d] += __shfl_xor_sync(0xffffffffu, vacc[d], 16);

  if (half16 == 0) {
    __nv_bfloat16 hh[8], ll[8];
#pragma unroll
    for (int i = 0; i < 8; i++) {
      hh[i] = __float2bfloat16(vacc[i]);
      ll[i] = __float2bfloat16(vacc[i] - __bfloat162float(hh[i]));
    }
    size_t base = (size_t)token * D1 + h * EMB + s16 * 8;
    *(uint4*)&g_aoh[base] = *(uint4*)hh;
    *(uint4*)&g_aol[base] = *(uint4*)ll;
  }
}

// ---------------- Kernel 4: output GEMM (64x128 tile, split-K x4) -----------
__global__ __launch_bounds__(256) void out_gemm() {
  extern __shared__ __nv_bfloat16 dsm[];
  __nv_bfloat16* sAh = dsm;
  __nv_bfloat16* sAl = dsm + 2 * ASTG;
  __nv_bfloat16* sBh = dsm + 4 * ASTG;
  __nv_bfloat16* sBl = dsm + 4 * ASTG + 2 * BSTG;
  int bm = blockIdx.x, kslice = blockIdx.y;
  int tid = threadIdx.x, wid = tid >> 5, lane = tid & 31;
  int wm = wid >> 2, wn = wid & 3;     // 2 x 4 warps, warp tile 32x32
  float acc[2][4][4] = {};
  int kbase = kslice * 256;

  int rA = tid >> 2, cA = tid & 3;                 // 64 rows x 4 chunks
  int rB0 = tid >> 2, cB0 = tid & 3;               // 128 rows x 4 chunks
  int rB1 = (tid + 256) >> 2, cB1 = (tid + 256) & 3;

  auto load_stage = [&](int st, int kc) {
    int soA = st * ASTG + rA * SPAD + cA * 8;
    int soB0 = st * BSTG + rB0 * SPAD + cB0 * 8;
    int soB1 = st * BSTG + rB1 * SPAD + cB1 * 8;
    size_t ga = (size_t)(bm * 64 + rA) * D1 + kc + cA * 8;
    size_t gb0 = (size_t)rB0 * D1 + kc + cB0 * 8;
    size_t gb1 = (size_t)rB1 * D1 + kc + cB1 * 8;
    cpa16(&sAh[soA], &g_aoh[ga]);
    cpa16(&sAl[soA], &g_aol[ga]);
    cpa16(&sBh[soB0], &g_Wuth[gb0]); cpa16(&sBh[soB1], &g_Wuth[gb1]);
    cpa16(&sBl[soB0], &g_Wutl[gb0]); cpa16(&sBl[soB1], &g_Wutl[gb1]);
    CP_COMMIT();
  };

  load_stage(0, kbase);
#pragma unroll
  for (int kci = 0; kci < 8; kci++) {
    if (kci < 7) load_stage((kci + 1) & 1, kbase + (kci + 1) * 32);
    if (kci < 7) { CP_WAIT1(); } else { CP_WAIT0(); }
    __syncthreads();
    __nv_bfloat16* pAh = sAh + (kci & 1) * ASTG;
    __nv_bfloat16* pAl = sAl + (kci & 1) * ASTG;
    __nv_bfloat16* pBh = sBh + (kci & 1) * BSTG;
    __nv_bfloat16* pBl = sBl + (kci & 1) * BSTG;
#pragma unroll
    for (int ks = 0; ks < 32; ks += 16) {
      uint32_t Ah[2][4], Al[2][4], Bh[2][4], Bl[2][4];
#pragma unroll
      for (int mt = 0; mt < 2; mt++) {
        int off = (wm * 32 + mt * 16 + (lane & 15)) * SPAD + ks + 8 * (lane >> 4);
        ldsm4(Ah[mt], &pAh[off]);
        ldsm4(Al[mt], &pAl[off]);
      }
#pragma unroll
      for (int nb = 0; nb < 2; nb++) {
        int off = (wn * 32 + nb * 16 + 8 * ((lane >> 4) & 1) + (lane & 7)) * SPAD
                  + ks + 8 * ((lane >> 3) & 1);
        ldsm4(Bh[nb], &pBh[off]);
        ldsm4(Bl[nb], &pBl[off]);
      }
#pragma unroll
      for (int mt = 0; mt < 2; mt++)
#pragma unroll
        for (int nb = 0; nb < 2; nb++) {
          mma16816(acc[mt][nb * 2],     Ah[mt], &Bh[nb][0]);
          mma16816(acc[mt][nb * 2],     Ah[mt], &Bl[nb][0]);
          mma16816(acc[mt][nb * 2],     Al[mt], &Bh[nb][0]);
          mma16816(acc[mt][nb * 2 + 1], Ah[mt], &Bh[nb][2]);
          mma16816(acc[mt][nb * 2 + 1], Ah[mt], &Bl[nb][2]);
          mma16816(acc[mt][nb * 2 + 1], Al[mt], &Bh[nb][2]);
        }
    }
    __syncthreads();
  }

  int g = lane >> 2, t = lane & 3;
  float* dst = g_part[kslice];
#pragma unroll
  for (int mt = 0; mt < 2; mt++)
#pragma unroll
    for (int nt = 0; nt < 4; nt++) {
      int row = bm * 64 + wm * 32 + mt * 16 + g;
      int col = wn * 32 + nt * 8 + 2 * t;
      *(float2*)&dst[(size_t)row * 128 + col] =
          make_float2(acc[mt][nt][0], acc[mt][nt][1]);
      *(float2*)&dst[(size_t)(row + 8) * 128 + col] =
          make_float2(acc[mt][nt][2], acc[mt][nt][3]);
    }
}

// Deterministic reduce of the 4 split-K partials + bias.
__global__ __launch_bounds__(256) void out_reduce(float* __restrict__ Cout,
                                                  const float* __restrict__ bu) {
  int e4 = blockIdx.x * 256 + threadIdx.x;   // float4 index, 0..131071
  int col0 = (e4 * 4) & 127;
  float4 s = *(const float4*)(bu + col0);
#pragma unroll
  for (int ks = 0; ks < 4; ks++) {
    float4 p = *(const float4*)(g_part[ks] + e4 * 4);
    s.x += p.x; s.y += p.y; s.z += p.z; s.w += p.w;
  }
  *(float4*)(Cout + e4 * 4) = s;
}

// ---------------- launch ----------------------------------------------------
extern "C" void kernel_launch(void* const* d_in, const int* in_sizes, int n_in,
                              void* d_out, int out_size) {
  const float* x   = (const float*)d_in[0];
  const float* sp  = (const float*)d_in[1];
  const float* mv  = (const float*)d_in[2];
  const float* Wq  = (const float*)d_in[3];
  const float* Wk  = (const float*)d_in[4];
  const float* Wv  = (const float*)d_in[5];
  const float* Wu  = (const float*)d_in[6];
  const float* bu  = (const float*)d_in[7];
  float* out = (float*)d_out;

  static cudaStream_t s2 = nullptr;
  static cudaEvent_t evFork = nullptr, evJoin = nullptr;
  if (!s2) {   // first call = uncaptured correctness run: safe to create
    cudaStreamCreateWithFlags(&s2, cudaStreamNonBlocking);
    cudaEventCreateWithFlags(&evFork, cudaEventDisableTiming);
    cudaEventCreateWithFlags(&evJoin, cudaEventDisableTiming);
    cudaFuncSetAttribute(qkv_gemm, cudaFuncAttributeMaxDynamicSharedMemorySize, DSMEM);
    cudaFuncSetAttribute(out_gemm, cudaFuncAttributeMaxDynamicSharedMemorySize, DSMEM2);
  }

  // fork: idxw (attn-only dependency) runs concurrently with X/W split + qkv
  cudaEventRecord(evFork, 0);
  cudaStreamWaitEvent(s2, evFork, 0);
  idxw_kernel<<<1024, 256, 0, s2>>>(sp, mv);
  cudaEventRecord(evJoin, s2);

  prepass_xw<<<1024, 256>>>(x, Wq, Wk, Wv, Wu);
  qkv_gemm<<<dim3(24, 32), 256, DSMEM>>>();

  cudaStreamWaitEvent(0, evJoin, 0);   // join before attn consumes g_idx/g_w
  attn_kernel<<<dim3(512, 8), 256>>>();
  out_gemm<<<dim3(64, 4), 256, DSMEM2>>>();
  out_reduce<<<512, 256>>>(out, bu);
}

// round 16
// speedup vs baseline: 1.3503x; 1.3005x over previous
#include <cuda_runtime.h>
#include <cuda_bf16.h>
#include <cuda_fp16.h>
#include <stdint.h>
#include <math.h>

// Problem constants
#define Tn    2048
#define EMB   128
#define NH    8
#define Mv    9      // M
#define Pp    36     // P
#define BT    4096   // B*T
#define D1    1024   // NH*EMB
#define D3    3072   // 3*D1
#define SPAD  40     // padded fp16 smem row stride (80B: ldmatrix conflict-free)
#define STG   (128 * SPAD)            // qkv: elems per stage per array
#define DSMEM (4 * STG * 2)           // qkv: 2 arrays x 2 stages (40960 B)
#define ASTG  (64 * SPAD)             // out: A elems per stage
#define BSTG  (128 * SPAD)            // out: B elems per stage
#define DSMEM2 ((2 * ASTG + 2 * BSTG) * 2)  // out: bytes (30720)

// Scratch (static device arrays; no allocation allowed)
__device__ __half g_q[BT * D1];            // Q fp16 (scaled), token-major
__device__ __half g_K[2 * NH * Tn * EMB];  // K fp16 (scaled), [b][h][t][d]
__device__ __half g_V[2 * NH * Tn * EMB];  // V fp16,          [b][h][t][d]
__device__ int   g_idx[BT * Pp];           // element offsets (j*EMB)
__device__ float g_w[BT * Pp];
__device__ float g_part[4][BT * 128];      // split-K partials for out gemm

// fp16 single-precision GEMM operands
__device__ __half g_Xf[BT * EMB];          // X fp16
__device__ __half g_Wtf[D3 * EMB];         // [Wq|Wk|Wv]^T [n][k] fp16
__device__ __half g_Wutf[EMB * D1];        // Wu^T [128][1024] fp16
__device__ __half g_aof[BT * D1];          // attn out fp16

// ---------------- threefry-2x32 (JAX-compatible, 20 rounds) ----------------
__device__ __forceinline__ void tf2x32(uint32_t k0, uint32_t k1,
                                       uint32_t& x0, uint32_t& x1) {
  uint32_t ks2 = k0 ^ k1 ^ 0x1BD11BDAu;
  x0 += k0; x1 += k1;
#define TFR(r) { x0 += x1; x1 = (x1 << (r)) | (x1 >> (32 - (r))); x1 ^= x0; }
  TFR(13) TFR(15) TFR(26) TFR(6)
  x0 += k1;  x1 += ks2 + 1u;
  TFR(17) TFR(29) TFR(16) TFR(24)
  x0 += ks2; x1 += k0 + 2u;
  TFR(13) TFR(15) TFR(26) TFR(6)
  x0 += k0;  x1 += k1 + 3u;
  TFR(17) TFR(29) TFR(16) TFR(24)
  x0 += k1;  x1 += ks2 + 4u;
  TFR(13) TFR(15) TFR(26) TFR(6)
  x0 += ks2; x1 += k0 + 5u;
#undef TFR
}

// ---------------- MMA / ldmatrix / cp.async helpers -------------------------
__device__ __forceinline__ void mma16816h(float* c, const uint32_t* a, const uint32_t* b) {
  asm volatile(
    "mma.sync.aligned.m16n8k16.row.col.f32.f16.f16.f32 "
    "{%0,%1,%2,%3}, {%4,%5,%6,%7}, {%8,%9}, {%0,%1,%2,%3};"
    : "+f"(c[0]), "+f"(c[1]), "+f"(c[2]), "+f"(c[3])
    : "r"(a[0]), "r"(a[1]), "r"(a[2]), "r"(a[3]), "r"(b[0]), "r"(b[1]));
}
__device__ __forceinline__ void ldsm4(uint32_t* r, const __half* p) {
  uint32_t a = (uint32_t)__cvta_generic_to_shared(p);
  asm volatile("ldmatrix.sync.aligned.m8n8.x4.shared.b16 {%0,%1,%2,%3}, [%4];"
               : "=r"(r[0]), "=r"(r[1]), "=r"(r[2]), "=r"(r[3]) : "r"(a));
}
__device__ __forceinline__ void cpa16(__half* dst, const __half* src) {
  uint32_t d = (uint32_t)__cvta_generic_to_shared(dst);
  asm volatile("cp.async.ca.shared.global [%0], [%1], 16;" :: "r"(d), "l"(src));
}
#define CP_COMMIT() asm volatile("cp.async.commit_group;")
#define CP_WAIT1()  asm volatile("cp.async.wait_group 1;" ::: "memory")
#define CP_WAIT0()  asm volatile("cp.async.wait_group 0;" ::: "memory")

// mixed-precision fma: f16 inputs, f32 accumulate (PTX ISA 8.6, sm_100+)
__device__ __forceinline__ void fmah(float& acc, unsigned short a, unsigned short b) {
  asm("fma.rn.f32.f16 %0, %1, %2, %0;" : "+f"(acc) : "h"(a), "h"(b));
}
__device__ __forceinline__ void unpack2(unsigned short& h0, unsigned short& h1, uint32_t w) {
  asm("mov.b32 {%0, %1}, %2;" : "=h"(h0), "=h"(h1) : "r"(w));
}
__device__ __forceinline__ float dot8h(uint4 q, uint4 k) {
  unsigned short qa, qb, ka, kb;
  float a0 = 0.f, a1 = 0.f;
  unpack2(qa, qb, q.x); unpack2(ka, kb, k.x);
  fmah(a0, qa, ka); fmah(a1, qb, kb);
  unpack2(qa, qb, q.y); unpack2(ka, kb, k.y);
  fmah(a0, qa, ka); fmah(a1, qb, kb);
  unpack2(qa, qb, q.z); unpack2(ka, kb, k.z);
  fmah(a0, qa, ka); fmah(a1, qb, kb);
  unpack2(qa, qb, q.w); unpack2(ka, kb, k.w);
  fmah(a0, qa, ka); fmah(a1, qb, kb);
  return a0 + a1;
}

// ---------------- Prepass A: convert X + transpose/convert weights ----------
__device__ void twsplit_h(const float* __restrict__ src,
                          __half* __restrict__ d,
                          int N, int Kd, int nofs, int bx, int by,
                          float* tile /*32x33*/) {
  int tx = threadIdx.x & 31, ty = threadIdx.x >> 5;   // 32 x 8
  int n0 = bx * 32, k0 = by * 32;
  for (int i = ty; i < 32; i += 8)
    tile[i * 33 + tx] = src[(size_t)(k0 + i) * N + n0 + tx];
  __syncthreads();
  for (int i = ty; i < 32; i += 8) {
    float v = tile[tx * 33 + i];                 // src[k0+tx][n0+i]
    d[(size_t)(nofs + n0 + i) * Kd + k0 + tx] = __float2half_rn(v);
  }
}

__global__ __launch_bounds__(256) void prepass_xw(const float* __restrict__ X,
                                                  const float* __restrict__ Wq,
                                                  const float* __restrict__ Wk,
                                                  const float* __restrict__ Wv,
                                                  const float* __restrict__ Wu) {
  __shared__ float tile[32 * 33];
  int bid = blockIdx.x;
  if (bid < 512) {                      // convert X
    int e4 = bid * 256 + threadIdx.x;
    float4 v = *(const float4*)(X + e4 * 4);
    __half2 h01 = __floats2half2_rn(v.x, v.y);
    __half2 h23 = __floats2half2_rn(v.z, v.w);
    uint2 o; o.x = *(uint32_t*)&h01; o.y = *(uint32_t*)&h23;
    *(uint2*)&g_Xf[e4 * 4] = o;
  } else {
    int r = bid - 512;                  // 0..511
    int which = r >> 7, sub = r & 127;
    if (which < 3) {                    // Wq/Wk/Wv
      const float* src = (which == 0) ? Wq : ((which == 1) ? Wk : Wv);
      twsplit_h(src, g_Wtf, 1024, 128, which * 1024, sub & 31, sub >> 5, tile);
    } else {                            // Wu
      twsplit_h(Wu, g_Wutf, 128, 1024, 0, sub & 3, sub >> 2, tile);
    }
  }
}

// ---------------- Prepass B: indices + weights (runs on side stream) -------
__global__ __launch_bounds__(256) void idxw_kernel(const float* __restrict__ sp,
                                                   const float* __restrict__ mvals) {
  int sub = threadIdx.x >> 6;          // 0..3 (4 tokens per 256-thr block)
  int p = threadIdx.x & 63;
  int token = blockIdx.x * 4 + sub;    // 0..4095
  int b = token >> 11, t = token & 2047;
  __shared__ float s_mean[4][Mv];
  __shared__ float s_sigma_inv;
  __shared__ int   s_idx[4][Pp];
  __shared__ float s_ptsfl[4][Pp];
  __shared__ float s_dens[4][Pp][Mv];
  __shared__ float s_colinv[4][Mv];

  float dil = sp[0];
  if (p < Mv) {
    float off = __fmul_rn((float)(p - 4), dil);
    float mu  = __fadd_rn((float)t, off);
    mu = fminf(fmaxf(mu, 0.0f), (float)(Tn - 1));
    s_mean[sub][p] = mu;
  }
  if (threadIdx.x == 0) {
    float s = sp[1] + 2.0f;                 // SIGMA_BOOST
    float sigma = log1pf(expf(s)) + 1e-7f;  // softplus + EPS
    s_sigma_inv = 1.0f / sigma;
  }
  __syncthreads();

  if (p < Pp) {
    int m = p >> 2, slot = p & 3;
    float fl = floorf(s_mean[sub][m]);
    float val;
    if (slot == 0) val = fl;
    else if (slot == 1) val = fl + 1.0f;
    else {
      // JAX partitionable threefry (verified in R2)
      uint32_t k2a = 0u, k2b = 1u;
      tf2x32(0u, 42u, k2a, k2b);
      uint32_t i = (uint32_t)(b * 36864 + t * 18 + m * 2 + (slot - 2));
      uint32_t x0 = 0u, x1 = i;
      tf2x32(k2a, k2b, x0, x1);
      uint32_t bits = x0 ^ x1;
      val = (float)(bits & 2047u);
    }
    val = fminf(fmaxf(val, 0.0f), (float)(Tn - 1));
    int iv = (int)val;
    s_idx[sub][p] = iv;
    s_ptsfl[sub][p] = (float)iv;
  }
  __syncthreads();

  if (p < Pp) {
    bool dup = false;
    int my = s_idx[sub][p];
    for (int q = 0; q < p; q++) dup |= (s_idx[sub][q] == my);
    float inv_s = s_sigma_inv;
#pragma unroll
    for (int m = 0; m < Mv; m++) {
      float d = (s_ptsfl[sub][p] - s_mean[sub][m]) * inv_s;
      s_dens[sub][p][m] = dup ? 0.0f : expf(-0.5f * d * d);
    }
  }
  __syncthreads();

  if (p < Mv) {
    float sum = 0.0f;
    for (int q = 0; q < Pp; q++) sum += s_dens[sub][q][p];
    s_colinv[sub][p] = 1.0f / sum;
  }
  __syncthreads();

  if (p < Pp) {
    float w = 0.0f;
#pragma unroll
    for (int m = 0; m < Mv; m++) w += s_dens[sub][p][m] * s_colinv[sub][m] * mvals[m];
    g_idx[token * Pp + p] = s_idx[sub][p] * EMB;   // element offset for attn
    g_w[token * Pp + p] = w;
  }
}

// ---------------- Kernel 1: fused QKV projection (fp16 tensor core) --------
__global__ __launch_bounds__(256) void qkv_gemm() {
  extern __shared__ __half dsm[];
  __half* sA = dsm;                 // 2 stages x STG
  __half* sB = dsm + 2 * STG;       // 2 stages x STG
  int bn = blockIdx.x, bm = blockIdx.y;
  int n_glob0 = bn * 128;
  int tid = threadIdx.x, wid = tid >> 5, lane = tid & 31;
  int wm = wid >> 1, wn = wid & 1;
  float acc[2][8][4] = {};

  int r0 = tid >> 2, c0 = tid & 3;
  int r1 = (tid + 256) >> 2, c1 = (tid + 256) & 3;

  auto load_stage = [&](int st, int kc) {
    int so0 = st * STG + r0 * SPAD + c0 * 8;
    int so1 = st * STG + r1 * SPAD + c1 * 8;
    size_t ga0 = (size_t)(bm * 128 + r0) * 128 + kc + c0 * 8;
    size_t ga1 = (size_t)(bm * 128 + r1) * 128 + kc + c1 * 8;
    size_t gb0 = (size_t)(n_glob0 + r0) * 128 + kc + c0 * 8;
    size_t gb1 = (size_t)(n_glob0 + r1) * 128 + kc + c1 * 8;
    cpa16(&sA[so0], &g_Xf[ga0]);   cpa16(&sA[so1], &g_Xf[ga1]);
    cpa16(&sB[so0], &g_Wtf[gb0]);  cpa16(&sB[so1], &g_Wtf[gb1]);
    CP_COMMIT();
  };

  load_stage(0, 0);
#pragma unroll
  for (int kci = 0; kci < 4; kci++) {
    if (kci < 3) load_stage((kci + 1) & 1, (kci + 1) * 32);
    if (kci < 3) { CP_WAIT1(); } else { CP_WAIT0(); }
    __syncthreads();
    __half* pA = sA + (kci & 1) * STG;
    __half* pB = sB + (kci & 1) * STG;
#pragma unroll
    for (int ks = 0; ks < 32; ks += 16) {
      uint32_t A[2][4], B[4][4];
#pragma unroll
      for (int mt = 0; mt < 2; mt++) {
        int off = (wm * 32 + mt * 16 + (lane & 15)) * SPAD + ks + 8 * (lane >> 4);
        ldsm4(A[mt], &pA[off]);
      }
#pragma unroll
      for (int nb = 0; nb < 4; nb++) {
        int off = (wn * 64 + nb * 16 + 8 * ((lane >> 4) & 1) + (lane & 7)) * SPAD
                  + ks + 8 * ((lane >> 3) & 1);
        ldsm4(B[nb], &pB[off]);
      }
#pragma unroll
      for (int mt = 0; mt < 2; mt++)
#pragma unroll
        for (int nb = 0; nb < 4; nb++) {
          mma16816h(acc[mt][nb * 2],     A[mt], &B[nb][0]);
          mma16816h(acc[mt][nb * 2 + 1], A[mt], &B[nb][2]);
        }
    }
    __syncthreads();
  }

  int g = lane >> 2, t = lane & 3;
  int seg = n_glob0 >> 10;                          // 0=Q 1=K 2=V
  float scale = (seg < 2) ? 0.29730177875068026f : 1.0f; // 1/128^0.25
#pragma unroll
  for (int mt = 0; mt < 2; mt++)
#pragma unroll
    for (int nt = 0; nt < 8; nt++) {
      int row = bm * 128 + wm * 32 + mt * 16 + g;
      int col = n_glob0 + wn * 64 + nt * 8 + 2 * t;
      float2 v0 = make_float2(acc[mt][nt][0] * scale, acc[mt][nt][1] * scale);
      float2 v1 = make_float2(acc[mt][nt][2] * scale, acc[mt][nt][3] * scale);
      if (seg == 0) {
        *(__half2*)&g_q[(size_t)row * D1 + col] = __float22half2_rn(v0);
        *(__half2*)&g_q[(size_t)(row + 8) * D1 + col] = __float22half2_rn(v1);
      } else {
        int c = col & 1023, h = c >> 7, d = c & 127;
        int b = row >> 11, tt = row & 2047;
        __half* dst = (seg == 1) ? g_K : g_V;
        size_t base = ((size_t)(b * NH + h) * Tn + tt) * EMB + d;
        *(__half2*)&dst[base] = __float22half2_rn(v0);
        *(__half2*)&dst[base + 8 * EMB] = __float22half2_rn(v1);
      }
    }
}

// ---------------- Kernel 3: gathered attention (256-thr CTA, fp16 probs) ---
__global__ __launch_bounds__(256) void attn_kernel() {
  __shared__ float s_logit[8][Pp];
  __shared__ unsigned short s_a[8][Pp];   // probs as fp16 bits
  int tid = threadIdx.x;
  int wid = tid >> 5, lane = tid & 31;
  int g = lane >> 3, sub = lane & 7;       // QK: 4 groups x 8 lanes
  int half16 = lane >> 4, s16 = lane & 15; // V: 2 halves x 16 lanes
  int token = blockIdx.x * 8 + wid;
  int h = blockIdx.y;
  int b = token >> 11;

  const __half* qp = g_q + (size_t)token * D1 + h * EMB;
  const int*   ip = g_idx + token * Pp;
  const float* wp = g_w + token * Pp;
  const __half* kb = g_K + (size_t)(b * NH + h) * Tn * EMB;
  const __half* vb = g_V + (size_t)(b * NH + h) * Tn * EMB;

  uint4 q0 = *(const uint4*)&qp[sub * 8];        // 8 fp16
  uint4 q1 = *(const uint4*)&qp[64 + sub * 8];   // 8 fp16

#pragma unroll
  for (int it = 0; it < 9; it++) {
    int p = it * 4 + g;
    int j = ip[p];                                // element offset (j*EMB)
    const __half* kr = kb + j;
    uint4 k0 = *(const uint4*)&kr[sub * 8];
    uint4 k1 = *(const uint4*)&kr[64 + sub * 8];
    float d = dot8h(q0, k0) + dot8h(q1, k1);
    d += __shfl_xor_sync(0xffffffffu, d, 4);
    d += __shfl_xor_sync(0xffffffffu, d, 2);
    d += __shfl_xor_sync(0xffffffffu, d, 1);
    if (sub == 0) s_logit[wid][p] = wp[p] * d;
  }
  __syncwarp();

  float l0 = s_logit[wid][lane];
  float l1 = (lane < 4) ? s_logit[wid][32 + lane] : -1e30f;
  float mx = fmaxf(l0, l1);
#pragma unroll
  for (int o = 16; o >= 1; o >>= 1)
    mx = fmaxf(mx, __shfl_xor_sync(0xffffffffu, mx, o));
  float a0 = __expf(l0 - mx);
  float a1 = (lane < 4) ? __expf(l1 - mx) : 0.0f;
  float sm = a0 + a1;
#pragma unroll
  for (int o = 16; o >= 1; o >>= 1)
    sm += __shfl_xor_sync(0xffffffffu, sm, o);
  float inv = 1.0f / sm;
  s_a[wid][lane] = __half_as_ushort(__float2half_rn(a0 * inv));
  if (lane < 4) s_a[wid][32 + lane] = __half_as_ushort(__float2half_rn(a1 * inv));
  __syncwarp();

  float vacc[8] = {};
#pragma unroll
  for (int it = 0; it < 18; it++) {
    int p = it * 2 + half16;
    int j = ip[p];                                // element offset
    unsigned short au = s_a[wid][p];
    uint4 v = *(const uint4*)&vb[j + s16 * 8];
    unsigned short v0, v1;
    unpack2(v0, v1, v.x); fmah(vacc[0], v0, au); fmah(vacc[1], v1, au);
    unpack2(v0, v1, v.y); fmah(vacc[2], v0, au); fmah(vacc[3], v1, au);
    unpack2(v0, v1, v.z); fmah(vacc[4], v0, au); fmah(vacc[5], v1, au);
    unpack2(v0, v1, v.w); fmah(vacc[6], v0, au); fmah(vacc[7], v1, au);
  }
#pragma unroll
  for (int d = 0; d < 8; d++)
    vacc[d] += __shfl_xor_sync(0xffffffffu, vacc[d], 16);

  if (half16 == 0) {
    __half2 o[4];
    o[0] = __floats2half2_rn(vacc[0], vacc[1]);
    o[1] = __floats2half2_rn(vacc[2], vacc[3]);
    o[2] = __floats2half2_rn(vacc[4], vacc[5]);
    o[3] = __floats2half2_rn(vacc[6], vacc[7]);
    size_t base = (size_t)token * D1 + h * EMB + s16 * 8;
    *(uint4*)&g_aof[base] = *(uint4*)o;
  }
}

// ---------------- Kernel 4: output GEMM (fp16, 64x128 tile, split-K x4) ----
__global__ __launch_bounds__(256) void out_gemm() {
  extern __shared__ __half dsm[];
  __half* sA = dsm;                  // 2 stages x ASTG
  __half* sB = dsm + 2 * ASTG;       // 2 stages x BSTG
  int bm = blockIdx.x, kslice = blockIdx.y;
  int tid = threadIdx.x, wid = tid >> 5, lane = tid & 31;
  int wm = wid >> 2, wn = wid & 3;     // 2 x 4 warps, warp tile 32x32
  float acc[2][4][4] = {};
  int kbase = kslice * 256;

  int rA = tid >> 2, cA = tid & 3;                 // 64 rows x 4 chunks
  int rB0 = tid >> 2, cB0 = tid & 3;               // 128 rows x 4 chunks
  int rB1 = (tid + 256) >> 2, cB1 = (tid + 256) & 3;

  auto load_stage = [&](int st, int kc) {
    int soA = st * ASTG + rA * SPAD + cA * 8;
    int soB0 = st * BSTG + rB0 * SPAD + cB0 * 8;
    int soB1 = st * BSTG + rB1 * SPAD + cB1 * 8;
    size_t ga = (size_t)(bm * 64 + rA) * D1 + kc + cA * 8;
    size_t gb0 = (size_t)rB0 * D1 + kc + cB0 * 8;
    size_t gb1 = (size_t)rB1 * D1 + kc + cB1 * 8;
    cpa16(&sA[soA], &g_aof[ga]);
    cpa16(&sB[soB0], &g_Wutf[gb0]); cpa16(&sB[soB1], &g_Wutf[gb1]);
    CP_COMMIT();
  };

  load_stage(0, kbase);
#pragma unroll
  for (int kci = 0; kci < 8; kci++) {
    if (kci < 7) load_stage((kci + 1) & 1, kbase + (kci + 1) * 32);
    if (kci < 7) { CP_WAIT1(); } else { CP_WAIT0(); }
    __syncthreads();
    __half* pA = sA + (kci & 1) * ASTG;
    __half* pB = sB + (kci & 1) * BSTG;
#pragma unroll
    for (int ks = 0; ks < 32; ks += 16) {
      uint32_t A[2][4], B[2][4];
#pragma unroll
      for (int mt = 0; mt < 2; mt++) {
        int off = (wm * 32 + mt * 16 + (lane & 15)) * SPAD + ks + 8 * (lane >> 4);
        ldsm4(A[mt], &pA[off]);
      }
#pragma unroll
      for (int nb = 0; nb < 2; nb++) {
        int off = (wn * 32 + nb * 16 + 8 * ((lane >> 4) & 1) + (lane & 7)) * SPAD
                  + ks + 8 * ((lane >> 3) & 1);
        ldsm4(B[nb], &pB[off]);
      }
#pragma unroll
      for (int mt = 0; mt < 2; mt++)
#pragma unroll
        for (int nb = 0; nb < 2; nb++) {
          mma16816h(acc[mt][nb * 2],     A[mt], &B[nb][0]);
          mma16816h(acc[mt][nb * 2 + 1], A[mt], &B[nb][2]);
        }
    }
    __syncthreads();
  }

  int g = lane >> 2, t = lane & 3;
  float* dst = g_part[kslice];
#pragma unroll
  for (int mt = 0; mt < 2; mt++)
#pragma unroll
    for (int nt = 0; nt < 4; nt++) {
      int row = bm * 64 + wm * 32 + mt * 16 + g;
      int col = wn * 32 + nt * 8 + 2 * t;
      *(float2*)&dst[(size_t)row * 128 + col] =
          make_float2(acc[mt][nt][0], acc[mt][nt][1]);
      *(float2*)&dst[(size_t)(row + 8) * 128 + col] =
          make_float2(acc[mt][nt][2], acc[mt][nt][3]);
    }
}

// Deterministic reduce of the 4 split-K partials + bias.
__global__ __launch_bounds__(256) void out_reduce(float* __restrict__ Cout,
                                                  const float* __restrict__ bu) {
  int e4 = blockIdx.x * 256 + threadIdx.x;   // float4 index, 0..131071
  int col0 = (e4 * 4) & 127;
  float4 s = *(const float4*)(bu + col0);
#pragma unroll
  for (int ks = 0; ks < 4; ks++) {
    float4 p = *(const float4*)(g_part[ks] + e4 * 4);
    s.x += p.x; s.y += p.y; s.z += p.z; s.w += p.w;
  }
  *(float4*)(Cout + e4 * 4) = s;
}

// ---------------- launch ----------------------------------------------------
extern "C" void kernel_launch(void* const* d_in, const int* in_sizes, int n_in,
                              void* d_out, int out_size) {
  const float* x   = (const float*)d_in[0];
  const float* sp  = (const float*)d_in[1];
  const float* mv  = (const float*)d_in[2];
  const float* Wq  = (const float*)d_in[3];
  const float* Wk  = (const float*)d_in[4];
  const float* Wv  = (const float*)d_in[5];
  const float* Wu  = (const float*)d_in[6];
  const float* bu  = (const float*)d_in[7];
  float* out = (float*)d_out;

  static cudaStream_t s2 = nullptr;
  static cudaEvent_t evFork = nullptr, evJoin = nullptr;
  if (!s2) {   // first call = uncaptured correctness run: safe to create
    cudaStreamCreateWithFlags(&s2, cudaStreamNonBlocking);
    cudaEventCreateWithFlags(&evFork, cudaEventDisableTiming);
    cudaEventCreateWithFlags(&evJoin, cudaEventDisableTiming);
    cudaFuncSetAttribute(qkv_gemm, cudaFuncAttributeMaxDynamicSharedMemorySize, DSMEM);
    cudaFuncSetAttribute(out_gemm, cudaFuncAttributeMaxDynamicSharedMemorySize, DSMEM2);
  }

  // fork: idxw (attn-only dependency) runs concurrently with X/W conv + qkv
  cudaEventRecord(evFork, 0);
  cudaStreamWaitEvent(s2, evFork, 0);
  idxw_kernel<<<1024, 256, 0, s2>>>(sp, mv);
  cudaEventRecord(evJoin, s2);

  prepass_xw<<<1024, 256>>>(x, Wq, Wk, Wv, Wu);
  qkv_gemm<<<dim3(24, 32), 256, DSMEM>>>();

  cudaStreamWaitEvent(0, evJoin, 0);   // join before attn consumes g_idx/g_w
  attn_kernel<<<dim3(512, 8), 256>>>();
  out_gemm<<<dim3(64, 4), 256, DSMEM2>>>();
  out_reduce<<<512, 256>>>(out, bu);
}

// round 17
// speedup vs baseline: 1.4520x; 1.0753x over previous
#include <cuda_runtime.h>
#include <cuda_bf16.h>
#include <cuda_fp16.h>
#include <stdint.h>
#include <math.h>

// Problem constants
#define Tn    2048
#define EMB   128
#define NH    8
#define Mv    9      // M
#define Pp    36     // P
#define BT    4096   // B*T
#define D1    1024   // NH*EMB
#define D3    3072   // 3*D1
#define SPAD  40     // padded fp16 smem row stride (80B: ldmatrix conflict-free)
#define STG   (128 * SPAD)            // qkv: elems per stage per array
#define DSMEM (4 * STG * 2)           // qkv: 2 arrays x 2 stages (40960 B)
#define ASTG  (64 * SPAD)             // out: A elems per stage
#define BSTG  (128 * SPAD)            // out: B elems per stage
#define DSMEM2 ((2 * ASTG + 2 * BSTG) * 2)  // out: bytes (30720)

// Scratch (static device arrays; no allocation allowed)
__device__ __half g_q[BT * D1];            // Q fp16 (scaled), token-major
__device__ __half g_K[2 * NH * Tn * EMB];  // K fp16 (scaled), [b][h][t][d]
__device__ __half g_V[2 * NH * Tn * EMB];  // V fp16,          [b][h][t][d]
__device__ int   g_idx[BT * Pp];           // element offsets (j*EMB)
__device__ float g_w[BT * Pp];
__device__ float g_part[4][BT * 128];      // split-K partials for out gemm

// fp16 single-precision GEMM operands
__device__ __half g_Xf[BT * EMB];          // X fp16
__device__ __half g_Wtf[D3 * EMB];         // [Wq|Wk|Wv]^T [n][k] fp16
__device__ __half g_Wutf[EMB * D1];        // Wu^T [128][1024] fp16
__device__ __half g_aof[BT * D1];          // attn out fp16

// ---------------- threefry-2x32 (JAX-compatible, 20 rounds) ----------------
__device__ __forceinline__ void tf2x32(uint32_t k0, uint32_t k1,
                                       uint32_t& x0, uint32_t& x1) {
  uint32_t ks2 = k0 ^ k1 ^ 0x1BD11BDAu;
  x0 += k0; x1 += k1;
#define TFR(r) { x0 += x1; x1 = (x1 << (r)) | (x1 >> (32 - (r))); x1 ^= x0; }
  TFR(13) TFR(15) TFR(26) TFR(6)
  x0 += k1;  x1 += ks2 + 1u;
  TFR(17) TFR(29) TFR(16) TFR(24)
  x0 += ks2; x1 += k0 + 2u;
  TFR(13) TFR(15) TFR(26) TFR(6)
  x0 += k0;  x1 += k1 + 3u;
  TFR(17) TFR(29) TFR(16) TFR(24)
  x0 += k1;  x1 += ks2 + 4u;
  TFR(13) TFR(15) TFR(26) TFR(6)
  x0 += ks2; x1 += k0 + 5u;
#undef TFR
}

// ---------------- MMA / ldmatrix / cp.async helpers -------------------------
__device__ __forceinline__ void mma16816h(float* c, const uint32_t* a, const uint32_t* b) {
  asm volatile(
    "mma.sync.aligned.m16n8k16.row.col.f32.f16.f16.f32 "
    "{%0,%1,%2,%3}, {%4,%5,%6,%7}, {%8,%9}, {%0,%1,%2,%3};"
    : "+f"(c[0]), "+f"(c[1]), "+f"(c[2]), "+f"(c[3])
    : "r"(a[0]), "r"(a[1]), "r"(a[2]), "r"(a[3]), "r"(b[0]), "r"(b[1]));
}
__device__ __forceinline__ void ldsm4(uint32_t* r, const __half* p) {
  uint32_t a = (uint32_t)__cvta_generic_to_shared(p);
  asm volatile("ldmatrix.sync.aligned.m8n8.x4.shared.b16 {%0,%1,%2,%3}, [%4];"
               : "=r"(r[0]), "=r"(r[1]), "=r"(r[2]), "=r"(r[3]) : "r"(a));
}
__device__ __forceinline__ void cpa16(__half* dst, const __half* src) {
  uint32_t d = (uint32_t)__cvta_generic_to_shared(dst);
  asm volatile("cp.async.ca.shared.global [%0], [%1], 16;" :: "r"(d), "l"(src));
}
#define CP_COMMIT() asm volatile("cp.async.commit_group;")
#define CP_WAIT1()  asm volatile("cp.async.wait_group 1;" ::: "memory")
#define CP_WAIT0()  asm volatile("cp.async.wait_group 0;" ::: "memory")

// mixed-precision fma: f16 inputs, f32 accumulate (PTX ISA 8.6, sm_100+)
__device__ __forceinline__ void fmah(float& acc, unsigned short a, unsigned short b) {
  asm("fma.rn.f32.f16 %0, %1, %2, %0;" : "+f"(acc) : "h"(a), "h"(b));
}
__device__ __forceinline__ void unpack2(unsigned short& h0, unsigned short& h1, uint32_t w) {
  asm("mov.b32 {%0, %1}, %2;" : "=h"(h0), "=h"(h1) : "r"(w));
}
__device__ __forceinline__ float dot8h(uint4 q, uint4 k) {
  unsigned short qa, qb, ka, kb;
  float a0 = 0.f, a1 = 0.f;
  unpack2(qa, qb, q.x); unpack2(ka, kb, k.x);
  fmah(a0, qa, ka); fmah(a1, qb, kb);
  unpack2(qa, qb, q.y); unpack2(ka, kb, k.y);
  fmah(a0, qa, ka); fmah(a1, qb, kb);
  unpack2(qa, qb, q.z); unpack2(ka, kb, k.z);
  fmah(a0, qa, ka); fmah(a1, qb, kb);
  unpack2(qa, qb, q.w); unpack2(ka, kb, k.w);
  fmah(a0, qa, ka); fmah(a1, qb, kb);
  return a0 + a1;
}

// ---------------- Prepass A: convert X + transpose/convert weights ----------
__device__ void twsplit_h(const float* __restrict__ src,
                          __half* __restrict__ d,
                          int N, int Kd, int nofs, int bx, int by,
                          float* tile /*32x33*/) {
  int tx = threadIdx.x & 31, ty = threadIdx.x >> 5;   // 32 x 8
  int n0 = bx * 32, k0 = by * 32;
  for (int i = ty; i < 32; i += 8)
    tile[i * 33 + tx] = src[(size_t)(k0 + i) * N + n0 + tx];
  __syncthreads();
  for (int i = ty; i < 32; i += 8) {
    float v = tile[tx * 33 + i];                 // src[k0+tx][n0+i]
    d[(size_t)(nofs + n0 + i) * Kd + k0 + tx] = __float2half_rn(v);
  }
}

__global__ __launch_bounds__(256) void prepass_xw(const float* __restrict__ X,
                                                  const float* __restrict__ Wq,
                                                  const float* __restrict__ Wk,
                                                  const float* __restrict__ Wv,
                                                  const float* __restrict__ Wu) {
  __shared__ float tile[32 * 33];
  int bid = blockIdx.x;
  if (bid < 512) {                      // convert X
    int e4 = bid * 256 + threadIdx.x;
    float4 v = *(const float4*)(X + e4 * 4);
    __half2 h01 = __floats2half2_rn(v.x, v.y);
    __half2 h23 = __floats2half2_rn(v.z, v.w);
    uint2 o; o.x = *(uint32_t*)&h01; o.y = *(uint32_t*)&h23;
    *(uint2*)&g_Xf[e4 * 4] = o;
  } else {
    int r = bid - 512;                  // 0..511
    int which = r >> 7, sub = r & 127;
    if (which < 3) {                    // Wq/Wk/Wv
      const float* src = (which == 0) ? Wq : ((which == 1) ? Wk : Wv);
      twsplit_h(src, g_Wtf, 1024, 128, which * 1024, sub & 31, sub >> 5, tile);
    } else {                            // Wu
      twsplit_h(Wu, g_Wutf, 128, 1024, 0, sub & 3, sub >> 2, tile);
    }
  }
}

// ---------------- Prepass B: indices + weights (runs on side stream) -------
__global__ __launch_bounds__(256) void idxw_kernel(const float* __restrict__ sp,
                                                   const float* __restrict__ mvals) {
  int sub = threadIdx.x >> 6;          // 0..3 (4 tokens per 256-thr block)
  int p = threadIdx.x & 63;
  int token = blockIdx.x * 4 + sub;    // 0..4095
  int b = token >> 11, t = token & 2047;
  __shared__ float s_mean[4][Mv];
  __shared__ float s_sigma_inv;
  __shared__ int   s_idx[4][Pp];
  __shared__ float s_ptsfl[4][Pp];
  __shared__ float s_dens[4][Pp][Mv];
  __shared__ float s_colinv[4][Mv];

  float dil = sp[0];
  if (p < Mv) {
    float off = __fmul_rn((float)(p - 4), dil);
    float mu  = __fadd_rn((float)t, off);
    mu = fminf(fmaxf(mu, 0.0f), (float)(Tn - 1));
    s_mean[sub][p] = mu;
  }
  if (threadIdx.x == 0) {
    float s = sp[1] + 2.0f;                 // SIGMA_BOOST
    float sigma = log1pf(expf(s)) + 1e-7f;  // softplus + EPS
    s_sigma_inv = 1.0f / sigma;
  }
  __syncthreads();

  if (p < Pp) {
    int m = p >> 2, slot = p & 3;
    float fl = floorf(s_mean[sub][m]);
    float val;
    if (slot == 0) val = fl;
    else if (slot == 1) val = fl + 1.0f;
    else {
      // JAX partitionable threefry (verified in R2)
      uint32_t k2a = 0u, k2b = 1u;
      tf2x32(0u, 42u, k2a, k2b);
      uint32_t i = (uint32_t)(b * 36864 + t * 18 + m * 2 + (slot - 2));
      uint32_t x0 = 0u, x1 = i;
      tf2x32(k2a, k2b, x0, x1);
      uint32_t bits = x0 ^ x1;
      val = (float)(bits & 2047u);
    }
    val = fminf(fmaxf(val, 0.0f), (float)(Tn - 1));
    int iv = (int)val;
    s_idx[sub][p] = iv;
    s_ptsfl[sub][p] = (float)iv;
  }
  __syncthreads();

  if (p < Pp) {
    bool dup = false;
    int my = s_idx[sub][p];
    for (int q = 0; q < p; q++) dup |= (s_idx[sub][q] == my);
    float inv_s = s_sigma_inv;
#pragma unroll
    for (int m = 0; m < Mv; m++) {
      float d = (s_ptsfl[sub][p] - s_mean[sub][m]) * inv_s;
      s_dens[sub][p][m] = dup ? 0.0f : expf(-0.5f * d * d);
    }
  }
  __syncthreads();

  if (p < Mv) {
    float sum = 0.0f;
    for (int q = 0; q < Pp; q++) sum += s_dens[sub][q][p];
    s_colinv[sub][p] = 1.0f / sum;
  }
  __syncthreads();

  if (p < Pp) {
    float w = 0.0f;
#pragma unroll
    for (int m = 0; m < Mv; m++) w += s_dens[sub][p][m] * s_colinv[sub][m] * mvals[m];
    g_idx[token * Pp + p] = s_idx[sub][p] * EMB;   // element offset for attn
    g_w[token * Pp + p] = w;
  }
}

// ---------------- Kernel 1: fused QKV projection (fp16 tensor core) --------
__global__ __launch_bounds__(256) void qkv_gemm() {
  extern __shared__ __half dsm[];
  __half* sA = dsm;                 // 2 stages x STG
  __half* sB = dsm + 2 * STG;       // 2 stages x STG
  int bn = blockIdx.x, bm = blockIdx.y;
  int n_glob0 = bn * 128;
  int tid = threadIdx.x, wid = tid >> 5, lane = tid & 31;
  int wm = wid >> 1, wn = wid & 1;
  float acc[2][8][4] = {};

  int r0 = tid >> 2, c0 = tid & 3;
  int r1 = (tid + 256) >> 2, c1 = (tid + 256) & 3;

  auto load_stage = [&](int st, int kc) {
    int so0 = st * STG + r0 * SPAD + c0 * 8;
    int so1 = st * STG + r1 * SPAD + c1 * 8;
    size_t ga0 = (size_t)(bm * 128 + r0) * 128 + kc + c0 * 8;
    size_t ga1 = (size_t)(bm * 128 + r1) * 128 + kc + c1 * 8;
    size_t gb0 = (size_t)(n_glob0 + r0) * 128 + kc + c0 * 8;
    size_t gb1 = (size_t)(n_glob0 + r1) * 128 + kc + c1 * 8;
    cpa16(&sA[so0], &g_Xf[ga0]);   cpa16(&sA[so1], &g_Xf[ga1]);
    cpa16(&sB[so0], &g_Wtf[gb0]);  cpa16(&sB[so1], &g_Wtf[gb1]);
    CP_COMMIT();
  };

  load_stage(0, 0);
#pragma unroll
  for (int kci = 0; kci < 4; kci++) {
    if (kci < 3) load_stage((kci + 1) & 1, (kci + 1) * 32);
    if (kci < 3) { CP_WAIT1(); } else { CP_WAIT0(); }
    __syncthreads();
    __half* pA = sA + (kci & 1) * STG;
    __half* pB = sB + (kci & 1) * STG;
#pragma unroll
    for (int ks = 0; ks < 32; ks += 16) {
      uint32_t A[2][4], B[4][4];
#pragma unroll
      for (int mt = 0; mt < 2; mt++) {
        int off = (wm * 32 + mt * 16 + (lane & 15)) * SPAD + ks + 8 * (lane >> 4);
        ldsm4(A[mt], &pA[off]);
      }
#pragma unroll
      for (int nb = 0; nb < 4; nb++) {
        int off = (wn * 64 + nb * 16 + 8 * ((lane >> 4) & 1) + (lane & 7)) * SPAD
                  + ks + 8 * ((lane >> 3) & 1);
        ldsm4(B[nb], &pB[off]);
      }
#pragma unroll
      for (int mt = 0; mt < 2; mt++)
#pragma unroll
        for (int nb = 0; nb < 4; nb++) {
          mma16816h(acc[mt][nb * 2],     A[mt], &B[nb][0]);
          mma16816h(acc[mt][nb * 2 + 1], A[mt], &B[nb][2]);
        }
    }
    __syncthreads();
  }

  int g = lane >> 2, t = lane & 3;
  int seg = n_glob0 >> 10;                          // 0=Q 1=K 2=V
  float scale = (seg < 2) ? 0.29730177875068026f : 1.0f; // 1/128^0.25
#pragma unroll
  for (int mt = 0; mt < 2; mt++)
#pragma unroll
    for (int nt = 0; nt < 8; nt++) {
      int row = bm * 128 + wm * 32 + mt * 16 + g;
      int col = n_glob0 + wn * 64 + nt * 8 + 2 * t;
      float2 v0 = make_float2(acc[mt][nt][0] * scale, acc[mt][nt][1] * scale);
      float2 v1 = make_float2(acc[mt][nt][2] * scale, acc[mt][nt][3] * scale);
      if (seg == 0) {
        *(__half2*)&g_q[(size_t)row * D1 + col] = __float22half2_rn(v0);
        *(__half2*)&g_q[(size_t)(row + 8) * D1 + col] = __float22half2_rn(v1);
      } else {
        int c = col & 1023, h = c >> 7, d = c & 127;
        int b = row >> 11, tt = row & 2047;
        __half* dst = (seg == 1) ? g_K : g_V;
        size_t base = ((size_t)(b * NH + h) * Tn + tt) * EMB + d;
        *(__half2*)&dst[base] = __float22half2_rn(v0);
        *(__half2*)&dst[base + 8 * EMB] = __float22half2_rn(v1);
      }
    }
}

// ---------------- Kernel 3: gathered attention (dup-K-skip, fp16 probs) ----
__global__ __launch_bounds__(256) void attn_kernel() {
  __shared__ float s_logit[8][Pp];
  __shared__ unsigned short s_a[8][Pp];   // probs as fp16 bits
  int tid = threadIdx.x;
  int wid = tid >> 5, lane = tid & 31;
  int g = lane >> 3, sub = lane & 7;       // QK: 4 groups x 8 lanes
  int half16 = lane >> 4, s16 = lane & 15; // V: 2 halves x 16 lanes
  int token = blockIdx.x * 8 + wid;
  int h = blockIdx.y;
  int b = token >> 11;

  const __half* qp = g_q + (size_t)token * D1 + h * EMB;
  const int*   ip = g_idx + token * Pp;
  const float* wp = g_w + token * Pp;
  const __half* kb = g_K + (size_t)(b * NH + h) * Tn * EMB;
  const __half* vb = g_V + (size_t)(b * NH + h) * Tn * EMB;

  uint4 q0 = *(const uint4*)&qp[sub * 8];        // 8 fp16
  uint4 q1 = *(const uint4*)&qp[64 + sub * 8];   // 8 fp16

#pragma unroll
  for (int it = 0; it < 9; it++) {
    int p = it * 4 + g;
    float w = wp[p];
    float d = 0.0f;
    // dup points have w == 0 exactly -> logit = 0 regardless of dot:
    // skip the K gather entirely (saves L1 wavefronts; bit-identical result).
    if (w != 0.0f) {
      int j = ip[p];                              // element offset (j*EMB)
      const __half* kr = kb + j;
      uint4 k0 = *(const uint4*)&kr[sub * 8];
      uint4 k1 = *(const uint4*)&kr[64 + sub * 8];
      d = dot8h(q0, k0) + dot8h(q1, k1);
    }
    d += __shfl_xor_sync(0xffffffffu, d, 4);
    d += __shfl_xor_sync(0xffffffffu, d, 2);
    d += __shfl_xor_sync(0xffffffffu, d, 1);
    if (sub == 0) s_logit[wid][p] = w * d;
  }
  __syncwarp();

  float l0 = s_logit[wid][lane];
  float l1 = (lane < 4) ? s_logit[wid][32 + lane] : -1e30f;
  float mx = fmaxf(l0, l1);
#pragma unroll
  for (int o = 16; o >= 1; o >>= 1)
    mx = fmaxf(mx, __shfl_xor_sync(0xffffffffu, mx, o));
  float a0 = __expf(l0 - mx);
  float a1 = (lane < 4) ? __expf(l1 - mx) : 0.0f;
  float sm = a0 + a1;
#pragma unroll
  for (int o = 16; o >= 1; o >>= 1)
    sm += __shfl_xor_sync(0xffffffffu, sm, o);
  float inv = 1.0f / sm;
  s_a[wid][lane] = __half_as_ushort(__float2half_rn(a0 * inv));
  if (lane < 4) s_a[wid][32 + lane] = __half_as_ushort(__float2half_rn(a1 * inv));
  __syncwarp();

  float vacc[8] = {};
#pragma unroll
  for (int it = 0; it < 18; it++) {
    int p = it * 2 + half16;
    int j = ip[p];                                // element offset
    unsigned short au = s_a[wid][p];
    uint4 v = *(const uint4*)&vb[j + s16 * 8];
    unsigned short v0, v1;
    unpack2(v0, v1, v.x); fmah(vacc[0], v0, au); fmah(vacc[1], v1, au);
    unpack2(v0, v1, v.y); fmah(vacc[2], v0, au); fmah(vacc[3], v1, au);
    unpack2(v0, v1, v.z); fmah(vacc[4], v0, au); fmah(vacc[5], v1, au);
    unpack2(v0, v1, v.w); fmah(vacc[6], v0, au); fmah(vacc[7], v1, au);
  }
#pragma unroll
  for (int d = 0; d < 8; d++)
    vacc[d] += __shfl_xor_sync(0xffffffffu, vacc[d], 16);

  if (half16 == 0) {
    __half2 o[4];
    o[0] = __floats2half2_rn(vacc[0], vacc[1]);
    o[1] = __floats2half2_rn(vacc[2], vacc[3]);
    o[2] = __floats2half2_rn(vacc[4], vacc[5]);
    o[3] = __floats2half2_rn(vacc[6], vacc[7]);
    size_t base = (size_t)token * D1 + h * EMB + s16 * 8;
    *(uint4*)&g_aof[base] = *(uint4*)o;
  }
}

// ---------------- Kernel 4: output GEMM (fp16, 64x128 tile, split-K x4) ----
__global__ __launch_bounds__(256) void out_gemm() {
  extern __shared__ __half dsm[];
  __half* sA = dsm;                  // 2 stages x ASTG
  __half* sB = dsm + 2 * ASTG;       // 2 stages x BSTG
  int bm = blockIdx.x, kslice = blockIdx.y;
  int tid = threadIdx.x, wid = tid >> 5, lane = tid & 31;
  int wm = wid >> 2, wn = wid & 3;     // 2 x 4 warps, warp tile 32x32
  float acc[2][4][4] = {};
  int kbase = kslice * 256;

  int rA = tid >> 2, cA = tid & 3;                 // 64 rows x 4 chunks
  int rB0 = tid >> 2, cB0 = tid & 3;               // 128 rows x 4 chunks
  int rB1 = (tid + 256) >> 2, cB1 = (tid + 256) & 3;

  auto load_stage = [&](int st, int kc) {
    int soA = st * ASTG + rA * SPAD + cA * 8;
    int soB0 = st * BSTG + rB0 * SPAD + cB0 * 8;
    int soB1 = st * BSTG + rB1 * SPAD + cB1 * 8;
    size_t ga = (size_t)(bm * 64 + rA) * D1 + kc + cA * 8;
    size_t gb0 = (size_t)rB0 * D1 + kc + cB0 * 8;
    size_t gb1 = (size_t)rB1 * D1 + kc + cB1 * 8;
    cpa16(&sA[soA], &g_aof[ga]);
    cpa16(&sB[soB0], &g_Wutf[gb0]); cpa16(&sB[soB1], &g_Wutf[gb1]);
    CP_COMMIT();
  };

  load_stage(0, kbase);
#pragma unroll
  for (int kci = 0; kci < 8; kci++) {
    if (kci < 7) load_stage((kci + 1) & 1, kbase + (kci + 1) * 32);
    if (kci < 7) { CP_WAIT1(); } else { CP_WAIT0(); }
    __syncthreads();
    __half* pA = sA + (kci & 1) * ASTG;
    __half* pB = sB + (kci & 1) * BSTG;
#pragma unroll
    for (int ks = 0; ks < 32; ks += 16) {
      uint32_t A[2][4], B[2][4];
#pragma unroll
      for (int mt = 0; mt < 2; mt++) {
        int off = (wm * 32 + mt * 16 + (lane & 15)) * SPAD + ks + 8 * (lane >> 4);
        ldsm4(A[mt], &pA[off]);
      }
#pragma unroll
      for (int nb = 0; nb < 2; nb++) {
        int off = (wn * 32 + nb * 16 + 8 * ((lane >> 4) & 1) + (lane & 7)) * SPAD
                  + ks + 8 * ((lane >> 3) & 1);
        ldsm4(B[nb], &pB[off]);
      }
#pragma unroll
      for (int mt = 0; mt < 2; mt++)
#pragma unroll
        for (int nb = 0; nb < 2; nb++) {
          mma16816h(acc[mt][nb * 2],     A[mt], &B[nb][0]);
          mma16816h(acc[mt][nb * 2 + 1], A[mt], &B[nb][2]);
        }
    }
    __syncthreads();
  }

  int g = lane >> 2, t = lane & 3;
  float* dst = g_part[kslice];
#pragma unroll
  for (int mt = 0; mt < 2; mt++)
#pragma unroll
    for (int nt = 0; nt < 4; nt++) {
      int row = bm * 64 + wm * 32 + mt * 16 + g;
      int col = wn * 32 + nt * 8 + 2 * t;
      *(float2*)&dst[(size_t)row * 128 + col] =
          make_float2(acc[mt][nt][0], acc[mt][nt][1]);
      *(float2*)&dst[(size_t)(row + 8) * 128 + col] =
          make_float2(acc[mt][nt][2], acc[mt][nt][3]);
    }
}

// Deterministic reduce of the 4 split-K partials + bias (2 float4/thread).
__global__ __launch_bounds__(256) void out_reduce(float* __restrict__ Cout,
                                                  const float* __restrict__ bu) {
#pragma unroll
  for (int it = 0; it < 2; it++) {
    int e4 = blockIdx.x * 512 + it * 256 + threadIdx.x;   // 0..131071
    int col0 = (e4 * 4) & 127;
    float4 s = *(const float4*)(bu + col0);
#pragma unroll
    for (int ks = 0; ks < 4; ks++) {
      float4 p = *(const float4*)(g_part[ks] + e4 * 4);
      s.x += p.x; s.y += p.y; s.z += p.z; s.w += p.w;
    }
    *(float4*)(Cout + e4 * 4) = s;
  }
}

// ---------------- launch ----------------------------------------------------
extern "C" void kernel_launch(void* const* d_in, const int* in_sizes, int n_in,
                              void* d_out, int out_size) {
  const float* x   = (const float*)d_in[0];
  const float* sp  = (const float*)d_in[1];
  const float* mv  = (const float*)d_in[2];
  const float* Wq  = (const float*)d_in[3];
  const float* Wk  = (const float*)d_in[4];
  const float* Wv  = (const float*)d_in[5];
  const float* Wu  = (const float*)d_in[6];
  const float* bu  = (const float*)d_in[7];
  float* out = (float*)d_out;

  static cudaStream_t s2 = nullptr;
  static cudaEvent_t evFork = nullptr, evJoin = nullptr;
  if (!s2) {   // first call = uncaptured correctness run: safe to create
    cudaStreamCreateWithFlags(&s2, cudaStreamNonBlocking);
    cudaEventCreateWithFlags(&evFork, cudaEventDisableTiming);
    cudaEventCreateWithFlags(&evJoin, cudaEventDisableTiming);
    cudaFuncSetAttribute(qkv_gemm, cudaFuncAttributeMaxDynamicSharedMemorySize, DSMEM);
    cudaFuncSetAttribute(out_gemm, cudaFuncAttributeMaxDynamicSharedMemorySize, DSMEM2);
  }

  // fork: idxw (attn-only dependency) runs concurrently with X/W conv + qkv
  cudaEventRecord(evFork, 0);
  cudaStreamWaitEvent(s2, evFork, 0);
  idxw_kernel<<<1024, 256, 0, s2>>>(sp, mv);
  cudaEventRecord(evJoin, s2);

  prepass_xw<<<1024, 256>>>(x, Wq, Wk, Wv, Wu);
  qkv_gemm<<<dim3(24, 32), 256, DSMEM>>>();

  cudaStreamWaitEvent(0, evJoin, 0);   // join before attn consumes g_idx/g_w
  attn_kernel<<<dim3(512, 8), 256>>>();
  out_gemm<<<dim3(64, 4), 256, DSMEM2>>>();
  out_reduce<<<256, 256>>>(out, bu);
}